// round 12
// baseline (speedup 1.0000x reference)
#include <cuda_runtime.h>
#include <cuda_bf16.h>
#include <cstdint>
#include <math.h>

// Problem constants
namespace {
constexpr int B_   = 4;
constexpr int S_   = 2048;
constexpr int HID_ = 2048;
constexpr int H_   = 16;
constexpr int KV_  = 4;
constexpr int D_   = 128;
constexpr int G_   = H_ / KV_;
constexpr float EPS_   = 1e-6f;
constexpr float SCALE_ = 0.088388347648318447f; // 128^-0.5
constexpr int NQKV  = H_ * D_ + 2 * KV_ * D_;   // 3072
constexpr int KOFF  = H_ * D_;                  // 2048
constexpr int VOFF  = H_ * D_ + KV_ * D_;       // 2560
}

// ---------------------------------------------------------------------------
// Scratch — device globals (no cudaMalloc allowed)
// ---------------------------------------------------------------------------
__device__ float g_qkv[(size_t)B_ * S_ * NQKV];   // fused qkv projection fp32

__device__ __nv_bfloat16 g_Ahi[(size_t)B_ * S_ * HID_];
__device__ __nv_bfloat16 g_Alo[(size_t)B_ * S_ * HID_];
__device__ __nv_bfloat16 g_WqkvT_hi[(size_t)NQKV * HID_];
__device__ __nv_bfloat16 g_WqkvT_lo[(size_t)NQKV * HID_];
__device__ __nv_bfloat16 g_WoT_hi[(size_t)HID_ * H_ * D_];
__device__ __nv_bfloat16 g_WoT_lo[(size_t)HID_ * H_ * D_];

__device__ __nv_bfloat16 g_qhi[(size_t)B_ * S_ * H_ * D_];
__device__ __nv_bfloat16 g_qlo[(size_t)B_ * S_ * H_ * D_];
__device__ __nv_bfloat16 g_khi[(size_t)B_ * S_ * KV_ * D_];
__device__ __nv_bfloat16 g_klo[(size_t)B_ * S_ * KV_ * D_];
__device__ __nv_bfloat16 g_vthi[(size_t)B_ * KV_ * D_ * S_];  // [b][kv][d][s]
__device__ __nv_bfloat16 g_vtlo[(size_t)B_ * KV_ * D_ * S_];

// ---------------------------------------------------------------------------
// Helpers
// ---------------------------------------------------------------------------
__device__ __forceinline__ void mma_bf16(float* c, const uint32_t* a,
                                         uint32_t b0, uint32_t b1) {
    asm volatile(
        "mma.sync.aligned.m16n8k16.row.col.f32.bf16.bf16.f32 "
        "{%0,%1,%2,%3}, {%4,%5,%6,%7}, {%8,%9}, {%0,%1,%2,%3};"
        : "+f"(c[0]), "+f"(c[1]), "+f"(c[2]), "+f"(c[3])
        : "r"(a[0]), "r"(a[1]), "r"(a[2]), "r"(a[3]), "r"(b0), "r"(b1));
}

// Warp-collective ldmatrix x4: each thread passes its own row address.
__device__ __forceinline__ void ldmx4(uint32_t* r, const __nv_bfloat16* p) {
    uint32_t a = (uint32_t)__cvta_generic_to_shared(p);
    asm volatile("ldmatrix.sync.aligned.m8n8.x4.shared.b16 {%0,%1,%2,%3}, [%4];"
        : "=r"(r[0]), "=r"(r[1]), "=r"(r[2]), "=r"(r[3]) : "r"(a));
}

__device__ __forceinline__ void split2(float v, __nv_bfloat16& h, __nv_bfloat16& l) {
    h = __float2bfloat16(v);
    l = __float2bfloat16(v - __bfloat162float(h));
}

__device__ __forceinline__ uint32_t packbf(__nv_bfloat16 a, __nv_bfloat16 b) {
    __nv_bfloat162 v = __halves2bfloat162(a, b);
    return *(uint32_t*)&v;
}

__device__ __forceinline__ void cp16(void* s, const void* g) {
    uint32_t sa = (uint32_t)__cvta_generic_to_shared(s);
    asm volatile("cp.async.ca.shared.global [%0], [%1], 16;" :: "r"(sa), "l"(g));
}
#define CP_COMMIT() asm volatile("cp.async.commit_group;" ::: "memory")
#define CP_WAIT(n)  asm volatile("cp.async.wait_group %0;" :: "n"(n) : "memory")

// ---------------------------------------------------------------------------
// Split kernels
// ---------------------------------------------------------------------------
__global__ __launch_bounds__(256) void split_kernel(
    const float* __restrict__ X, __nv_bfloat16* __restrict__ hi,
    __nv_bfloat16* __restrict__ lo, int n4)
{
    int i = blockIdx.x * blockDim.x + threadIdx.x;
    int stride = gridDim.x * blockDim.x;
    for (; i < n4; i += stride) {
        float4 v = ((const float4*)X)[i];
        __nv_bfloat16 h0, h1, h2, h3, l0, l1, l2, l3;
        split2(v.x, h0, l0); split2(v.y, h1, l1);
        split2(v.z, h2, l2); split2(v.w, h3, l3);
        ((__nv_bfloat162*)hi)[i * 2]     = __halves2bfloat162(h0, h1);
        ((__nv_bfloat162*)hi)[i * 2 + 1] = __halves2bfloat162(h2, h3);
        ((__nv_bfloat162*)lo)[i * 2]     = __halves2bfloat162(l0, l1);
        ((__nv_bfloat162*)lo)[i * 2 + 1] = __halves2bfloat162(l2, l3);
    }
}

// W[Kd, Nd] fp32 -> hiT/loT [Nd, Kd] bf16 (transposed split)
__global__ __launch_bounds__(256) void split_T_kernel(
    const float* __restrict__ W, __nv_bfloat16* __restrict__ hiT,
    __nv_bfloat16* __restrict__ loT, int Kd, int Nd)
{
    __shared__ float t[32][33];
    const int bn = blockIdx.x * 32;
    const int bk = blockIdx.y * 32;
    const int tx = threadIdx.x, ty = threadIdx.y;
    #pragma unroll
    for (int i = ty; i < 32; i += 8)
        t[i][tx] = W[(size_t)(bk + i) * Nd + bn + tx];
    __syncthreads();
    #pragma unroll
    for (int i = ty; i < 32; i += 8) {
        float v = t[tx][i];
        __nv_bfloat16 h, l;
        split2(v, h, l);
        hiT[(size_t)(bn + i) * Kd + bk + tx] = h;
        loT[(size_t)(bn + i) * Kd + bk + tx] = l;
    }
}

// V fp32 (inside g_qkv, row stride NQKV) -> Vt hi/lo bf16 [b,kv,d,s]
__global__ __launch_bounds__(256) void vt_split_kernel()
{
    __shared__ float t[32][33];
    const int b  = blockIdx.z / KV_;
    const int kv = blockIdx.z % KV_;
    const int s0 = blockIdx.x * 32;
    const int d0 = blockIdx.y * 32;
    const int tx = threadIdx.x, ty = threadIdx.y;
    #pragma unroll
    for (int i = ty; i < 32; i += 8)
        t[i][tx] = g_qkv[((size_t)b * S_ + s0 + i) * NQKV + VOFF + kv * D_ + d0 + tx];
    __syncthreads();
    #pragma unroll
    for (int i = ty; i < 32; i += 8) {
        float v = t[tx][i];
        __nv_bfloat16 h, l;
        split2(v, h, l);
        size_t o = (((size_t)b * KV_ + kv) * D_ + d0 + i) * S_ + s0 + tx;
        g_vthi[o] = h;
        g_vtlo[o] = l;
    }
}

// ---------------------------------------------------------------------------
// Pipelined mma.sync GEMM: C = A @ B^T, bf16x3 (pass-major stages).
// CTA 128x128, 8 warps, 2-stage cp.async double buffer; ldmatrix fragments.
// 73728 B dyn smem -> 2 CTAs/SM.  (R7 config — proven fastest across probes)
// ---------------------------------------------------------------------------
constexpr int MMP   = 72;
constexpr int MMT   = 128 * MMP;        // 9216 bf16 per tile
constexpr int MMSTG = 2 * MMT;          // A + B tile
constexpr int MM_SMEM = 2 * MMSTG * 2;  // 73728 bytes

__global__ __launch_bounds__(256, 2) void mm_mma_kernel(
    const __nv_bfloat16* __restrict__ Ahi, const __nv_bfloat16* __restrict__ Alo,
    const __nv_bfloat16* __restrict__ Bhi, const __nv_bfloat16* __restrict__ Blo,
    float* __restrict__ C, int M, int N, int K)
{
    extern __shared__ char smc[];
    __nv_bfloat16* bufs = (__nv_bfloat16*)smc;   // 2 stages of MMSTG

    const int tid  = threadIdx.x;
    const int wid  = tid >> 5;
    const int lane = tid & 31;
    const int g    = lane >> 2;
    const int t    = lane & 3;
    const int wr   = wid >> 1;
    const int wc   = wid & 1;
    const int m0 = blockIdx.y * 128;
    const int n0 = blockIdx.x * 128;

    const int lm_r = lane & 15;
    const int lm_c = (lane >> 4) * 8;

    float acc[2][8][4];
    #pragma unroll
    for (int mb = 0; mb < 2; mb++)
        #pragma unroll
        for (int nb = 0; nb < 8; nb++)
            #pragma unroll
            for (int e = 0; e < 4; e++) acc[mb][nb][e] = 0.f;

    const int cpp   = K / 64;
    const int total = 3 * cpp;

    auto issue = [&](int s) {
        const int pass = s / cpp;
        const int kc   = (s - pass * cpp) * 64;
        const __nv_bfloat16* Ap = (pass == 2) ? Alo : Ahi;
        const __nv_bfloat16* Bp = (pass == 1) ? Blo : Bhi;
        __nv_bfloat16* st = bufs + (s & 1) * MMSTG;
        #pragma unroll
        for (int i = 0; i < 4; i++) {
            int idx = tid + i * 256;
            int row = idx >> 3;
            int c   = (idx & 7) * 8;
            cp16(st + row * MMP + c,       &Ap[(size_t)(m0 + row) * K + kc + c]);
            cp16(st + MMT + row * MMP + c, &Bp[(size_t)(n0 + row) * K + kc + c]);
        }
        CP_COMMIT();
    };

    issue(0);

    for (int s = 0; s < total; ++s) {
        if (s + 1 < total) { issue(s + 1); CP_WAIT(1); }
        else               { CP_WAIT(0); }
        __syncthreads();

        const __nv_bfloat16* As = bufs + (s & 1) * MMSTG;
        const __nv_bfloat16* Bs = As + MMT;
        #pragma unroll
        for (int ks = 0; ks < 4; ks++) {
            const int k0 = ks * 16;
            uint32_t a[2][4];
            #pragma unroll
            for (int mb = 0; mb < 2; mb++)
                ldmx4(a[mb], &As[(32 * wr + 16 * mb + lm_r) * MMP + k0 + lm_c]);
            uint32_t bb[4][4];
            #pragma unroll
            for (int p = 0; p < 4; p++)
                ldmx4(bb[p], &Bs[(64 * wc + 16 * p + lm_r) * MMP + k0 + lm_c]);
            #pragma unroll
            for (int p = 0; p < 4; p++) {
                mma_bf16(acc[0][2 * p],     a[0], bb[p][0], bb[p][2]);
                mma_bf16(acc[0][2 * p + 1], a[0], bb[p][1], bb[p][3]);
                mma_bf16(acc[1][2 * p],     a[1], bb[p][0], bb[p][2]);
                mma_bf16(acc[1][2 * p + 1], a[1], bb[p][1], bb[p][3]);
            }
        }
        __syncthreads();
    }

    #pragma unroll
    for (int mb = 0; mb < 2; mb++) {
        int row0 = m0 + 32 * wr + 16 * mb + g;
        #pragma unroll
        for (int nb = 0; nb < 8; nb++) {
            int col = n0 + 64 * wc + 8 * nb + 2 * t;
            *(float2*)&C[(size_t)row0 * N + col] =
                make_float2(acc[mb][nb][0], acc[mb][nb][1]);
            *(float2*)&C[(size_t)(row0 + 8) * N + col] =
                make_float2(acc[mb][nb][2], acc[mb][nb][3]);
        }
    }
}

// ---------------------------------------------------------------------------
// Fused RMSNorm + RoPE -> bf16 hi/lo. Input rows inside g_qkv (stride NQKV).
// ---------------------------------------------------------------------------
__global__ __launch_bounds__(256) void norm_rope_split_kernel(
    const float* __restrict__ x, int in_stride,
    const float* __restrict__ cosb, const float* __restrict__ sinb,
    const float* __restrict__ w,
    __nv_bfloat16* __restrict__ hi, __nv_bfloat16* __restrict__ lo, int nheads)
{
    const int warp = (blockIdx.x * blockDim.x + threadIdx.x) >> 5;
    const int lane = threadIdx.x & 31;
    const int nrows = B_ * S_ * nheads;
    if (warp >= nrows) return;

    const int bs   = warp / nheads;
    const int head = warp - bs * nheads;
    const int s    = bs % S_;

    const float* row = x + (size_t)bs * in_stride + (size_t)head * D_;
    size_t obase = (size_t)bs * nheads * D_ + (size_t)head * D_;

    float x0 = row[lane];
    float x1 = row[lane + 32];
    float x2 = row[lane + 64];
    float x3 = row[lane + 96];

    float ss = x0 * x0 + x1 * x1 + x2 * x2 + x3 * x3;
    #pragma unroll
    for (int o = 16; o > 0; o >>= 1) ss += __shfl_xor_sync(0xffffffffu, ss, o);
    float inv = rsqrtf(ss * (1.0f / (float)D_) + EPS_);

    float n0 = x0 * inv * w[lane];
    float n1 = x1 * inv * w[lane + 32];
    float n2 = x2 * inv * w[lane + 64];
    float n3 = x3 * inv * w[lane + 96];

    const float* cr = cosb + (size_t)s * D_;
    const float* sr = sinb + (size_t)s * D_;

    float r0 = n0 * cr[lane]      - n2 * sr[lane];
    float r1 = n1 * cr[lane + 32] - n3 * sr[lane + 32];
    float r2 = n2 * cr[lane + 64] + n0 * sr[lane + 64];
    float r3 = n3 * cr[lane + 96] + n1 * sr[lane + 96];

    __nv_bfloat16 h, l;
    split2(r0, h, l); hi[obase + lane]      = h; lo[obase + lane]      = l;
    split2(r1, h, l); hi[obase + lane + 32] = h; lo[obase + lane + 32] = l;
    split2(r2, h, l); hi[obase + lane + 64] = h; lo[obase + lane + 64] = l;
    split2(r3, h, l); hi[obase + lane + 96] = h; lo[obase + lane + 96] = l;
}

// ---------------------------------------------------------------------------
// Flash attention, bf16x3, BM=64, 4 warps (128 threads), warp-owns-16-rows.
// Identical per-row math to R7; smem 106.5 KB -> 2 CTAs/SM so one CTA's HMMA
// overlaps the other's softmax/load phases.
// ---------------------------------------------------------------------------
constexpr int APIT = 136;
constexpr int TPIT = 72;
constexpr int AQSZ = 64 * APIT;    // Q tile (64 rows)
constexpr int AKSZ = 64 * APIT;    // K tile (64 tokens)
constexpr int AVSZ = 128 * TPIT;   // Vt tile (128 d x 64 tokens)
constexpr int ATT_SMEM = (2 * AQSZ + 2 * AKSZ + 2 * AVSZ) * 2;  // 106496 B

__global__ __launch_bounds__(128, 2) void attn_mma_kernel()
{
    extern __shared__ char smc[];
    __nv_bfloat16* Qh = (__nv_bfloat16*)smc;
    __nv_bfloat16* Ql = Qh + AQSZ;
    __nv_bfloat16* Kh = Ql + AQSZ;
    __nv_bfloat16* Kl = Kh + AKSZ;
    __nv_bfloat16* Vh = Kl + AKSZ;
    __nv_bfloat16* Vl = Vh + AVSZ;

    const int tid  = threadIdx.x;
    const int wid  = tid >> 5;      // 0..3
    const int lane = tid & 31;
    const int g    = lane >> 2;
    const int t    = lane & 3;

    const int m0  = blockIdx.x * 64;
    const int h   = blockIdx.y;
    const int b   = blockIdx.z;
    const int kvh = h / G_;

    const int lm_r = lane & 15;
    const int lm_c = (lane >> 4) * 8;

    // stage Q (64 rows x 128 d, hi+lo)
    {
        const __nv_bfloat16* qh = g_qhi + (((size_t)b * S_ + m0) * H_ + h) * D_;
        const __nv_bfloat16* ql = g_qlo + (((size_t)b * S_ + m0) * H_ + h) * D_;
        #pragma unroll
        for (int i = 0; i < 8; i++) {
            int idx = tid + i * 128;
            int r   = idx >> 4;
            int c   = (idx & 15) * 8;
            *(uint4*)&Qh[r * APIT + c] = *(const uint4*)&qh[(size_t)r * H_ * D_ + c];
            *(uint4*)&Ql[r * APIT + c] = *(const uint4*)&ql[(size_t)r * H_ * D_ + c];
        }
    }

    float o[16][4];
    #pragma unroll
    for (int j = 0; j < 16; j++)
        #pragma unroll
        for (int e = 0; e < 4; e++) o[j][e] = 0.f;
    float rmx0 = -3.0e38f, rmx1 = -3.0e38f;
    float rsm0 = 0.f, rsm1 = 0.f;

    const __nv_bfloat16* khb = g_khi + ((size_t)b * S_ * KV_ + kvh) * D_;
    const __nv_bfloat16* klb = g_klo + ((size_t)b * S_ * KV_ + kvh) * D_;
    const __nv_bfloat16* vhb = g_vthi + ((size_t)b * KV_ + kvh) * D_ * S_;
    const __nv_bfloat16* vlb = g_vtlo + ((size_t)b * KV_ + kvh) * D_ * S_;

    for (int t0 = 0; t0 < S_; t0 += 64) {
        __syncthreads();   // previous tile's V reads done before overwrite
        #pragma unroll
        for (int i = 0; i < 8; i++) {
            int idx = tid + i * 128;
            int r   = idx >> 4;
            int c   = (idx & 15) * 8;
            size_t go = (size_t)(t0 + r) * KV_ * D_ + c;
            *(uint4*)&Kh[r * APIT + c] = *(const uint4*)&khb[go];
            *(uint4*)&Kl[r * APIT + c] = *(const uint4*)&klb[go];
            int d  = idx >> 3;
            int c2 = (idx & 7) * 8;
            size_t gv = (size_t)d * S_ + t0 + c2;
            *(uint4*)&Vh[d * TPIT + c2] = *(const uint4*)&vhb[gv];
            *(uint4*)&Vl[d * TPIT + c2] = *(const uint4*)&vlb[gv];
        }
        __syncthreads();

        // ---- S = Q @ K^T (bf16x3, ldmatrix) ----
        float sacc[8][4];
        #pragma unroll
        for (int j = 0; j < 8; j++)
            #pragma unroll
            for (int e = 0; e < 4; e++) sacc[j][e] = 0.f;

        #pragma unroll
        for (int pass = 0; pass < 3; pass++) {
            const __nv_bfloat16* Aq = (pass == 2) ? Ql : Qh;
            const __nv_bfloat16* Bk = (pass == 1) ? Kl : Kh;
            #pragma unroll
            for (int ks = 0; ks < 8; ks++) {
                const int k0 = ks * 16;
                uint32_t a[4];
                ldmx4(a, &Aq[(16 * wid + lm_r) * APIT + k0 + lm_c]);
                uint32_t bb[4][4];
                #pragma unroll
                for (int p = 0; p < 4; p++)
                    ldmx4(bb[p], &Bk[(16 * p + lm_r) * APIT + k0 + lm_c]);
                #pragma unroll
                for (int p = 0; p < 4; p++) {
                    mma_bf16(sacc[2 * p],     a, bb[p][0], bb[p][2]);
                    mma_bf16(sacc[2 * p + 1], a, bb[p][1], bb[p][3]);
                }
            }
        }

        // ---- in-warp online softmax ----
        float mx0 = -3.0e38f, mx1 = -3.0e38f;
        #pragma unroll
        for (int j = 0; j < 8; j++) {
            #pragma unroll
            for (int e = 0; e < 4; e++) sacc[j][e] *= SCALE_;
            mx0 = fmaxf(mx0, fmaxf(sacc[j][0], sacc[j][1]));
            mx1 = fmaxf(mx1, fmaxf(sacc[j][2], sacc[j][3]));
        }
        mx0 = fmaxf(mx0, __shfl_xor_sync(0xffffffffu, mx0, 1));
        mx0 = fmaxf(mx0, __shfl_xor_sync(0xffffffffu, mx0, 2));
        mx1 = fmaxf(mx1, __shfl_xor_sync(0xffffffffu, mx1, 1));
        mx1 = fmaxf(mx1, __shfl_xor_sync(0xffffffffu, mx1, 2));

        float m0n = fmaxf(rmx0, mx0);
        float m1n = fmaxf(rmx1, mx1);
        float corr0 = __expf(rmx0 - m0n);
        float corr1 = __expf(rmx1 - m1n);

        // exp + register split of P into hi/lo A-fragment halves
        uint32_t ph0[8], ph1[8], pl0[8], pl1[8];
        float sum0 = 0.f, sum1 = 0.f;
        #pragma unroll
        for (int j = 0; j < 8; j++) {
            float p0 = __expf(sacc[j][0] - m0n);
            float p1 = __expf(sacc[j][1] - m0n);
            float p2 = __expf(sacc[j][2] - m1n);
            float p3 = __expf(sacc[j][3] - m1n);
            sum0 += p0 + p1;
            sum1 += p2 + p3;
            __nv_bfloat16 h0, h1, l0, l1;
            split2(p0, h0, l0); split2(p1, h1, l1);
            ph0[j] = packbf(h0, h1); pl0[j] = packbf(l0, l1);
            split2(p2, h0, l0); split2(p3, h1, l1);
            ph1[j] = packbf(h0, h1); pl1[j] = packbf(l0, l1);
        }
        sum0 += __shfl_xor_sync(0xffffffffu, sum0, 1);
        sum0 += __shfl_xor_sync(0xffffffffu, sum0, 2);
        sum1 += __shfl_xor_sync(0xffffffffu, sum1, 1);
        sum1 += __shfl_xor_sync(0xffffffffu, sum1, 2);

        rsm0 = rsm0 * corr0 + sum0;
        rsm1 = rsm1 * corr1 + sum1;
        rmx0 = m0n;
        rmx1 = m1n;

        #pragma unroll
        for (int j = 0; j < 16; j++) {
            o[j][0] *= corr0; o[j][1] *= corr0;
            o[j][2] *= corr1; o[j][3] *= corr1;
        }

        // ---- O += P @ V (bf16x3, P from registers) ----
        #pragma unroll
        for (int pass = 0; pass < 3; pass++) {
            const uint32_t* a0 = (pass == 2) ? pl0 : ph0;
            const uint32_t* a1 = (pass == 2) ? pl1 : ph1;
            const __nv_bfloat16* Vb = (pass == 1) ? Vl : Vh;
            #pragma unroll
            for (int ks = 0; ks < 4; ks++) {
                const int k0 = ks * 16;
                uint32_t a[4];
                a[0] = a0[2 * ks];
                a[1] = a1[2 * ks];
                a[2] = a0[2 * ks + 1];
                a[3] = a1[2 * ks + 1];
                #pragma unroll
                for (int p = 0; p < 8; p++) {
                    uint32_t bb[4];
                    ldmx4(bb, &Vb[(16 * p + lm_r) * TPIT + k0 + lm_c]);
                    mma_bf16(o[2 * p],     a, bb[0], bb[2]);
                    mma_bf16(o[2 * p + 1], a, bb[1], bb[3]);
                }
            }
        }
    }

    // epilogue: write bf16 hi/lo split directly (input to Wo GEMM)
    float inv0 = 1.0f / rsm0;
    float inv1 = 1.0f / rsm1;
    size_t row0 = ((size_t)b * S_ + m0 + 16 * wid + g) * H_ * D_;
    size_t row1 = row0 + (size_t)8 * H_ * D_;
    #pragma unroll
    for (int j = 0; j < 16; j++) {
        int col = h * D_ + 8 * j + 2 * t;
        __nv_bfloat16 h0, h1, l0, l1;
        split2(o[j][0] * inv0, h0, l0);
        split2(o[j][1] * inv0, h1, l1);
        *(__nv_bfloat162*)&g_Ahi[row0 + col] = __halves2bfloat162(h0, h1);
        *(__nv_bfloat162*)&g_Alo[row0 + col] = __halves2bfloat162(l0, l1);
        split2(o[j][2] * inv1, h0, l0);
        split2(o[j][3] * inv1, h1, l1);
        *(__nv_bfloat162*)&g_Ahi[row1 + col] = __halves2bfloat162(h0, h1);
        *(__nv_bfloat162*)&g_Alo[row1 + col] = __halves2bfloat162(l0, l1);
    }
}

// ---------------------------------------------------------------------------
// Launch
// ---------------------------------------------------------------------------
extern "C" void kernel_launch(void* const* d_in, const int* in_sizes, int n_in,
                              void* d_out, int out_size)
{
    const float* x    = (const float*)d_in[0];
    const float* cosb = (const float*)d_in[1];
    const float* sinb = (const float*)d_in[2];
    const float* Wq   = (const float*)d_in[3];
    const float* Wk   = (const float*)d_in[4];
    const float* Wv   = (const float*)d_in[5];
    const float* Wo   = (const float*)d_in[6];
    const float* qw   = (const float*)d_in[7];
    const float* kw   = (const float*)d_in[8];
    float* out = (float*)d_out;

    float* qkv;
    cudaGetSymbolAddress((void**)&qkv, g_qkv);
    __nv_bfloat16 *Ahi, *Alo, *WqkvTh, *WqkvTl, *WoTh, *WoTl;
    __nv_bfloat16 *qhi, *qlo, *khi, *klo;
    cudaGetSymbolAddress((void**)&Ahi,    g_Ahi);
    cudaGetSymbolAddress((void**)&Alo,    g_Alo);
    cudaGetSymbolAddress((void**)&WqkvTh, g_WqkvT_hi);
    cudaGetSymbolAddress((void**)&WqkvTl, g_WqkvT_lo);
    cudaGetSymbolAddress((void**)&WoTh,   g_WoT_hi);
    cudaGetSymbolAddress((void**)&WoTl,   g_WoT_lo);
    cudaGetSymbolAddress((void**)&qhi,    g_qhi);
    cudaGetSymbolAddress((void**)&qlo,    g_qlo);
    cudaGetSymbolAddress((void**)&khi,    g_khi);
    cudaGetSymbolAddress((void**)&klo,    g_klo);

    const int M = B_ * S_;
    const int n4x = M * HID_ / 4;

    cudaFuncSetAttribute(mm_mma_kernel,
                         cudaFuncAttributeMaxDynamicSharedMemorySize, MM_SMEM);
    cudaFuncSetAttribute(attn_mma_kernel,
                         cudaFuncAttributeMaxDynamicSharedMemorySize, ATT_SMEM);

    // Split input + weights (Wq/Wk/Wv concatenated along N into one buffer)
    split_kernel<<<4096, 256>>>(x, Ahi, Alo, n4x);
    split_T_kernel<<<dim3((H_ * D_) / 32, HID_ / 32), dim3(32, 8)>>>(
        Wq, WqkvTh, WqkvTl, HID_, H_ * D_);
    split_T_kernel<<<dim3((KV_ * D_) / 32, HID_ / 32), dim3(32, 8)>>>(
        Wk, WqkvTh + (size_t)KOFF * HID_, WqkvTl + (size_t)KOFF * HID_, HID_, KV_ * D_);
    split_T_kernel<<<dim3((KV_ * D_) / 32, HID_ / 32), dim3(32, 8)>>>(
        Wv, WqkvTh + (size_t)VOFF * HID_, WqkvTl + (size_t)VOFF * HID_, HID_, KV_ * D_);
    split_T_kernel<<<dim3(HID_ / 32, (H_ * D_) / 32), dim3(32, 8)>>>(
        Wo, WoTh, WoTl, H_ * D_, HID_);

    // Fused QKV projection (one GEMM, N=3072)
    mm_mma_kernel<<<dim3(NQKV / 128, M / 128), 256, MM_SMEM>>>(
        Ahi, Alo, WqkvTh, WqkvTl, qkv, M, NQKV, HID_);

    // RMSNorm + RoPE -> bf16 hi/lo
    norm_rope_split_kernel<<<(B_ * S_ * H_) / 8, 256>>>(
        qkv, NQKV, cosb, sinb, qw, qhi, qlo, H_);
    norm_rope_split_kernel<<<(B_ * S_ * KV_) / 8, 256>>>(
        qkv + KOFF, NQKV, cosb, sinb, kw, khi, klo, KV_);

    // V transpose + split
    vt_split_kernel<<<dim3(S_ / 32, D_ / 32, B_ * KV_), dim3(32, 8)>>>();

    // Attention (BM=64, 128 threads, 2 CTAs/SM; writes bf16 hi/lo into Ahi/Alo)
    attn_mma_kernel<<<dim3(S_ / 64, H_, B_), 128, ATT_SMEM>>>();

    // Output projection
    mm_mma_kernel<<<dim3(HID_ / 128, M / 128), 256, MM_SMEM>>>(
        Ahi, Alo, WoTh, WoTl, out, M, HID_, HID_);
}

// round 13
// speedup vs baseline: 1.0389x; 1.0389x over previous
#include <cuda_runtime.h>
#include <cuda_bf16.h>
#include <cstdint>
#include <math.h>

// Problem constants
namespace {
constexpr int B_   = 4;
constexpr int S_   = 2048;
constexpr int HID_ = 2048;
constexpr int H_   = 16;
constexpr int KV_  = 4;
constexpr int D_   = 128;
constexpr int G_   = H_ / KV_;
constexpr float EPS_   = 1e-6f;
constexpr float SCALE_ = 0.088388347648318447f; // 128^-0.5
constexpr int NQKV  = H_ * D_ + 2 * KV_ * D_;   // 3072
constexpr int KOFF  = H_ * D_;                  // 2048
constexpr int VOFF  = H_ * D_ + KV_ * D_;       // 2560
}

// ---------------------------------------------------------------------------
// Scratch — device globals (no cudaMalloc allowed)
// ---------------------------------------------------------------------------
__device__ float g_qkv[(size_t)B_ * S_ * NQKV];   // fused qkv projection fp32

__device__ __nv_bfloat16 g_Ahi[(size_t)B_ * S_ * HID_];
__device__ __nv_bfloat16 g_Alo[(size_t)B_ * S_ * HID_];
__device__ __nv_bfloat16 g_WqkvT_hi[(size_t)NQKV * HID_];
__device__ __nv_bfloat16 g_WqkvT_lo[(size_t)NQKV * HID_];
__device__ __nv_bfloat16 g_WoT_hi[(size_t)HID_ * H_ * D_];
__device__ __nv_bfloat16 g_WoT_lo[(size_t)HID_ * H_ * D_];

__device__ __nv_bfloat16 g_qhi[(size_t)B_ * S_ * H_ * D_];
__device__ __nv_bfloat16 g_qlo[(size_t)B_ * S_ * H_ * D_];
__device__ __nv_bfloat16 g_khi[(size_t)B_ * S_ * KV_ * D_];
__device__ __nv_bfloat16 g_klo[(size_t)B_ * S_ * KV_ * D_];
__device__ __nv_bfloat16 g_vthi[(size_t)B_ * KV_ * D_ * S_];  // [b][kv][d][s]
__device__ __nv_bfloat16 g_vtlo[(size_t)B_ * KV_ * D_ * S_];

// ---------------------------------------------------------------------------
// Helpers
// ---------------------------------------------------------------------------
__device__ __forceinline__ void mma_bf16(float* c, const uint32_t* a,
                                         uint32_t b0, uint32_t b1) {
    asm volatile(
        "mma.sync.aligned.m16n8k16.row.col.f32.bf16.bf16.f32 "
        "{%0,%1,%2,%3}, {%4,%5,%6,%7}, {%8,%9}, {%0,%1,%2,%3};"
        : "+f"(c[0]), "+f"(c[1]), "+f"(c[2]), "+f"(c[3])
        : "r"(a[0]), "r"(a[1]), "r"(a[2]), "r"(a[3]), "r"(b0), "r"(b1));
}

// Warp-collective ldmatrix x4: each thread passes its own row address.
__device__ __forceinline__ void ldmx4(uint32_t* r, const __nv_bfloat16* p) {
    uint32_t a = (uint32_t)__cvta_generic_to_shared(p);
    asm volatile("ldmatrix.sync.aligned.m8n8.x4.shared.b16 {%0,%1,%2,%3}, [%4];"
        : "=r"(r[0]), "=r"(r[1]), "=r"(r[2]), "=r"(r[3]) : "r"(a));
}

__device__ __forceinline__ void split2(float v, __nv_bfloat16& h, __nv_bfloat16& l) {
    h = __float2bfloat16(v);
    l = __float2bfloat16(v - __bfloat162float(h));
}

__device__ __forceinline__ uint32_t packbf(__nv_bfloat16 a, __nv_bfloat16 b) {
    __nv_bfloat162 v = __halves2bfloat162(a, b);
    return *(uint32_t*)&v;
}

__device__ __forceinline__ void cp16(void* s, const void* g) {
    uint32_t sa = (uint32_t)__cvta_generic_to_shared(s);
    asm volatile("cp.async.ca.shared.global [%0], [%1], 16;" :: "r"(sa), "l"(g));
}
#define CP_COMMIT() asm volatile("cp.async.commit_group;" ::: "memory")
#define CP_WAIT(n)  asm volatile("cp.async.wait_group %0;" :: "n"(n) : "memory")

// ---------------------------------------------------------------------------
// Split kernels
// ---------------------------------------------------------------------------
__global__ __launch_bounds__(256) void split_kernel(
    const float* __restrict__ X, __nv_bfloat16* __restrict__ hi,
    __nv_bfloat16* __restrict__ lo, int n4)
{
    int i = blockIdx.x * blockDim.x + threadIdx.x;
    int stride = gridDim.x * blockDim.x;
    for (; i < n4; i += stride) {
        float4 v = ((const float4*)X)[i];
        __nv_bfloat16 h0, h1, h2, h3, l0, l1, l2, l3;
        split2(v.x, h0, l0); split2(v.y, h1, l1);
        split2(v.z, h2, l2); split2(v.w, h3, l3);
        ((__nv_bfloat162*)hi)[i * 2]     = __halves2bfloat162(h0, h1);
        ((__nv_bfloat162*)hi)[i * 2 + 1] = __halves2bfloat162(h2, h3);
        ((__nv_bfloat162*)lo)[i * 2]     = __halves2bfloat162(l0, l1);
        ((__nv_bfloat162*)lo)[i * 2 + 1] = __halves2bfloat162(l2, l3);
    }
}

// W[Kd, Nd] fp32 -> hiT/loT [Nd, Kd] bf16 (transposed split)
__global__ __launch_bounds__(256) void split_T_kernel(
    const float* __restrict__ W, __nv_bfloat16* __restrict__ hiT,
    __nv_bfloat16* __restrict__ loT, int Kd, int Nd)
{
    __shared__ float t[32][33];
    const int bn = blockIdx.x * 32;
    const int bk = blockIdx.y * 32;
    const int tx = threadIdx.x, ty = threadIdx.y;
    #pragma unroll
    for (int i = ty; i < 32; i += 8)
        t[i][tx] = W[(size_t)(bk + i) * Nd + bn + tx];
    __syncthreads();
    #pragma unroll
    for (int i = ty; i < 32; i += 8) {
        float v = t[tx][i];
        __nv_bfloat16 h, l;
        split2(v, h, l);
        hiT[(size_t)(bn + i) * Kd + bk + tx] = h;
        loT[(size_t)(bn + i) * Kd + bk + tx] = l;
    }
}

// V fp32 (inside g_qkv, row stride NQKV) -> Vt hi/lo bf16 [b,kv,d,s]
__global__ __launch_bounds__(256) void vt_split_kernel()
{
    __shared__ float t[32][33];
    const int b  = blockIdx.z / KV_;
    const int kv = blockIdx.z % KV_;
    const int s0 = blockIdx.x * 32;
    const int d0 = blockIdx.y * 32;
    const int tx = threadIdx.x, ty = threadIdx.y;
    #pragma unroll
    for (int i = ty; i < 32; i += 8)
        t[i][tx] = g_qkv[((size_t)b * S_ + s0 + i) * NQKV + VOFF + kv * D_ + d0 + tx];
    __syncthreads();
    #pragma unroll
    for (int i = ty; i < 32; i += 8) {
        float v = t[tx][i];
        __nv_bfloat16 h, l;
        split2(v, h, l);
        size_t o = (((size_t)b * KV_ + kv) * D_ + d0 + i) * S_ + s0 + tx;
        g_vthi[o] = h;
        g_vtlo[o] = l;
    }
}

// ---------------------------------------------------------------------------
// Pipelined mma.sync GEMM: C = A @ B^T, bf16x3 (pass-major stages).
// CTA 128x128, 8 warps, 2-stage cp.async double buffer; ldmatrix fragments.
// 73728 B dyn smem -> 2 CTAs/SM.  (R7 config — proven optimal across probes)
// ---------------------------------------------------------------------------
constexpr int MMP   = 72;
constexpr int MMT   = 128 * MMP;        // 9216 bf16 per tile
constexpr int MMSTG = 2 * MMT;          // A + B tile
constexpr int MM_SMEM = 2 * MMSTG * 2;  // 73728 bytes

__global__ __launch_bounds__(256, 2) void mm_mma_kernel(
    const __nv_bfloat16* __restrict__ Ahi, const __nv_bfloat16* __restrict__ Alo,
    const __nv_bfloat16* __restrict__ Bhi, const __nv_bfloat16* __restrict__ Blo,
    float* __restrict__ C, int M, int N, int K)
{
    extern __shared__ char smc[];
    __nv_bfloat16* bufs = (__nv_bfloat16*)smc;   // 2 stages of MMSTG

    const int tid  = threadIdx.x;
    const int wid  = tid >> 5;
    const int lane = tid & 31;
    const int g    = lane >> 2;
    const int t    = lane & 3;
    const int wr   = wid >> 1;
    const int wc   = wid & 1;
    const int m0 = blockIdx.y * 128;
    const int n0 = blockIdx.x * 128;

    const int lm_r = lane & 15;
    const int lm_c = (lane >> 4) * 8;

    float acc[2][8][4];
    #pragma unroll
    for (int mb = 0; mb < 2; mb++)
        #pragma unroll
        for (int nb = 0; nb < 8; nb++)
            #pragma unroll
            for (int e = 0; e < 4; e++) acc[mb][nb][e] = 0.f;

    const int cpp   = K / 64;
    const int total = 3 * cpp;

    auto issue = [&](int s) {
        const int pass = s / cpp;
        const int kc   = (s - pass * cpp) * 64;
        const __nv_bfloat16* Ap = (pass == 2) ? Alo : Ahi;
        const __nv_bfloat16* Bp = (pass == 1) ? Blo : Bhi;
        __nv_bfloat16* st = bufs + (s & 1) * MMSTG;
        #pragma unroll
        for (int i = 0; i < 4; i++) {
            int idx = tid + i * 256;
            int row = idx >> 3;
            int c   = (idx & 7) * 8;
            cp16(st + row * MMP + c,       &Ap[(size_t)(m0 + row) * K + kc + c]);
            cp16(st + MMT + row * MMP + c, &Bp[(size_t)(n0 + row) * K + kc + c]);
        }
        CP_COMMIT();
    };

    issue(0);

    for (int s = 0; s < total; ++s) {
        if (s + 1 < total) { issue(s + 1); CP_WAIT(1); }
        else               { CP_WAIT(0); }
        __syncthreads();

        const __nv_bfloat16* As = bufs + (s & 1) * MMSTG;
        const __nv_bfloat16* Bs = As + MMT;
        #pragma unroll
        for (int ks = 0; ks < 4; ks++) {
            const int k0 = ks * 16;
            uint32_t a[2][4];
            #pragma unroll
            for (int mb = 0; mb < 2; mb++)
                ldmx4(a[mb], &As[(32 * wr + 16 * mb + lm_r) * MMP + k0 + lm_c]);
            uint32_t bb[4][4];
            #pragma unroll
            for (int p = 0; p < 4; p++)
                ldmx4(bb[p], &Bs[(64 * wc + 16 * p + lm_r) * MMP + k0 + lm_c]);
            #pragma unroll
            for (int p = 0; p < 4; p++) {
                mma_bf16(acc[0][2 * p],     a[0], bb[p][0], bb[p][2]);
                mma_bf16(acc[0][2 * p + 1], a[0], bb[p][1], bb[p][3]);
                mma_bf16(acc[1][2 * p],     a[1], bb[p][0], bb[p][2]);
                mma_bf16(acc[1][2 * p + 1], a[1], bb[p][1], bb[p][3]);
            }
        }
        __syncthreads();
    }

    #pragma unroll
    for (int mb = 0; mb < 2; mb++) {
        int row0 = m0 + 32 * wr + 16 * mb + g;
        #pragma unroll
        for (int nb = 0; nb < 8; nb++) {
            int col = n0 + 64 * wc + 8 * nb + 2 * t;
            *(float2*)&C[(size_t)row0 * N + col] =
                make_float2(acc[mb][nb][0], acc[mb][nb][1]);
            *(float2*)&C[(size_t)(row0 + 8) * N + col] =
                make_float2(acc[mb][nb][2], acc[mb][nb][3]);
        }
    }
}

// ---------------------------------------------------------------------------
// Fused RMSNorm + RoPE -> bf16 hi/lo. Input rows inside g_qkv (stride NQKV).
// ---------------------------------------------------------------------------
__global__ __launch_bounds__(256) void norm_rope_split_kernel(
    const float* __restrict__ x, int in_stride,
    const float* __restrict__ cosb, const float* __restrict__ sinb,
    const float* __restrict__ w,
    __nv_bfloat16* __restrict__ hi, __nv_bfloat16* __restrict__ lo, int nheads)
{
    const int warp = (blockIdx.x * blockDim.x + threadIdx.x) >> 5;
    const int lane = threadIdx.x & 31;
    const int nrows = B_ * S_ * nheads;
    if (warp >= nrows) return;

    const int bs   = warp / nheads;
    const int head = warp - bs * nheads;
    const int s    = bs % S_;

    const float* row = x + (size_t)bs * in_stride + (size_t)head * D_;
    size_t obase = (size_t)bs * nheads * D_ + (size_t)head * D_;

    float x0 = row[lane];
    float x1 = row[lane + 32];
    float x2 = row[lane + 64];
    float x3 = row[lane + 96];

    float ss = x0 * x0 + x1 * x1 + x2 * x2 + x3 * x3;
    #pragma unroll
    for (int o = 16; o > 0; o >>= 1) ss += __shfl_xor_sync(0xffffffffu, ss, o);
    float inv = rsqrtf(ss * (1.0f / (float)D_) + EPS_);

    float n0 = x0 * inv * w[lane];
    float n1 = x1 * inv * w[lane + 32];
    float n2 = x2 * inv * w[lane + 64];
    float n3 = x3 * inv * w[lane + 96];

    const float* cr = cosb + (size_t)s * D_;
    const float* sr = sinb + (size_t)s * D_;

    float r0 = n0 * cr[lane]      - n2 * sr[lane];
    float r1 = n1 * cr[lane + 32] - n3 * sr[lane + 32];
    float r2 = n2 * cr[lane + 64] + n0 * sr[lane + 64];
    float r3 = n3 * cr[lane + 96] + n1 * sr[lane + 96];

    __nv_bfloat16 h, l;
    split2(r0, h, l); hi[obase + lane]      = h; lo[obase + lane]      = l;
    split2(r1, h, l); hi[obase + lane + 32] = h; lo[obase + lane + 32] = l;
    split2(r2, h, l); hi[obase + lane + 64] = h; lo[obase + lane + 64] = l;
    split2(r3, h, l); hi[obase + lane + 96] = h; lo[obase + lane + 96] = l;
}

// ---------------------------------------------------------------------------
// Flash attention, bf16x3, BM=128, warp-owns-rows layout (R7 — proven optimal).
// 8 warps; warp w owns q-rows [16w, 16w+16), all 64 S columns, full d=128 O.
// Softmax fully in-register/in-warp. P stays in registers (FA2 C->A reuse).
// ---------------------------------------------------------------------------
constexpr int APIT = 136;
constexpr int TPIT = 72;
constexpr int AQSZ = 128 * APIT;   // Q tile (128 rows)
constexpr int AKSZ = 64 * APIT;    // K tile (64 tokens)
constexpr int AVSZ = 128 * TPIT;   // Vt tile (128 d x 64 tokens)
constexpr int ATT_SMEM = (2 * AQSZ + 2 * AKSZ + 2 * AVSZ) * 2;  // 141312 B

__global__ __launch_bounds__(256) void attn_mma_kernel()
{
    extern __shared__ char smc[];
    __nv_bfloat16* Qh = (__nv_bfloat16*)smc;
    __nv_bfloat16* Ql = Qh + AQSZ;
    __nv_bfloat16* Kh = Ql + AQSZ;
    __nv_bfloat16* Kl = Kh + AKSZ;
    __nv_bfloat16* Vh = Kl + AKSZ;
    __nv_bfloat16* Vl = Vh + AVSZ;

    const int tid  = threadIdx.x;
    const int wid  = tid >> 5;
    const int lane = tid & 31;
    const int g    = lane >> 2;
    const int t    = lane & 3;

    const int m0  = blockIdx.x * 128;
    const int h   = blockIdx.y;
    const int b   = blockIdx.z;
    const int kvh = h / G_;

    const int lm_r = lane & 15;
    const int lm_c = (lane >> 4) * 8;

    // stage Q (128 rows x 128 d, hi+lo)
    {
        const __nv_bfloat16* qh = g_qhi + (((size_t)b * S_ + m0) * H_ + h) * D_;
        const __nv_bfloat16* ql = g_qlo + (((size_t)b * S_ + m0) * H_ + h) * D_;
        #pragma unroll
        for (int i = 0; i < 8; i++) {
            int idx = tid + i * 256;
            int r   = idx >> 4;
            int c   = (idx & 15) * 8;
            *(uint4*)&Qh[r * APIT + c] = *(const uint4*)&qh[(size_t)r * H_ * D_ + c];
            *(uint4*)&Ql[r * APIT + c] = *(const uint4*)&ql[(size_t)r * H_ * D_ + c];
        }
    }

    float o[16][4];
    #pragma unroll
    for (int j = 0; j < 16; j++)
        #pragma unroll
        for (int e = 0; e < 4; e++) o[j][e] = 0.f;
    float rmx0 = -3.0e38f, rmx1 = -3.0e38f;
    float rsm0 = 0.f, rsm1 = 0.f;

    const __nv_bfloat16* khb = g_khi + ((size_t)b * S_ * KV_ + kvh) * D_;
    const __nv_bfloat16* klb = g_klo + ((size_t)b * S_ * KV_ + kvh) * D_;
    const __nv_bfloat16* vhb = g_vthi + ((size_t)b * KV_ + kvh) * D_ * S_;
    const __nv_bfloat16* vlb = g_vtlo + ((size_t)b * KV_ + kvh) * D_ * S_;

    for (int t0 = 0; t0 < S_; t0 += 64) {
        __syncthreads();   // previous tile's V reads done before overwrite
        #pragma unroll
        for (int i = 0; i < 4; i++) {
            int idx = tid + i * 256;
            int r   = idx >> 4;
            int c   = (idx & 15) * 8;
            size_t go = (size_t)(t0 + r) * KV_ * D_ + c;
            *(uint4*)&Kh[r * APIT + c] = *(const uint4*)&khb[go];
            *(uint4*)&Kl[r * APIT + c] = *(const uint4*)&klb[go];
            int d  = idx >> 3;
            int c2 = (idx & 7) * 8;
            size_t gv = (size_t)d * S_ + t0 + c2;
            *(uint4*)&Vh[d * TPIT + c2] = *(const uint4*)&vhb[gv];
            *(uint4*)&Vl[d * TPIT + c2] = *(const uint4*)&vlb[gv];
        }
        __syncthreads();

        // ---- S = Q @ K^T (bf16x3, ldmatrix) ----
        float sacc[8][4];
        #pragma unroll
        for (int j = 0; j < 8; j++)
            #pragma unroll
            for (int e = 0; e < 4; e++) sacc[j][e] = 0.f;

        #pragma unroll
        for (int pass = 0; pass < 3; pass++) {
            const __nv_bfloat16* Aq = (pass == 2) ? Ql : Qh;
            const __nv_bfloat16* Bk = (pass == 1) ? Kl : Kh;
            #pragma unroll
            for (int ks = 0; ks < 8; ks++) {
                const int k0 = ks * 16;
                uint32_t a[4];
                ldmx4(a, &Aq[(16 * wid + lm_r) * APIT + k0 + lm_c]);
                uint32_t bb[4][4];
                #pragma unroll
                for (int p = 0; p < 4; p++)
                    ldmx4(bb[p], &Bk[(16 * p + lm_r) * APIT + k0 + lm_c]);
                #pragma unroll
                for (int p = 0; p < 4; p++) {
                    mma_bf16(sacc[2 * p],     a, bb[p][0], bb[p][2]);
                    mma_bf16(sacc[2 * p + 1], a, bb[p][1], bb[p][3]);
                }
            }
        }

        // ---- in-warp online softmax ----
        float mx0 = -3.0e38f, mx1 = -3.0e38f;
        #pragma unroll
        for (int j = 0; j < 8; j++) {
            #pragma unroll
            for (int e = 0; e < 4; e++) sacc[j][e] *= SCALE_;
            mx0 = fmaxf(mx0, fmaxf(sacc[j][0], sacc[j][1]));
            mx1 = fmaxf(mx1, fmaxf(sacc[j][2], sacc[j][3]));
        }
        mx0 = fmaxf(mx0, __shfl_xor_sync(0xffffffffu, mx0, 1));
        mx0 = fmaxf(mx0, __shfl_xor_sync(0xffffffffu, mx0, 2));
        mx1 = fmaxf(mx1, __shfl_xor_sync(0xffffffffu, mx1, 1));
        mx1 = fmaxf(mx1, __shfl_xor_sync(0xffffffffu, mx1, 2));

        float m0n = fmaxf(rmx0, mx0);
        float m1n = fmaxf(rmx1, mx1);
        float corr0 = __expf(rmx0 - m0n);
        float corr1 = __expf(rmx1 - m1n);

        // exp + register split of P into hi/lo A-fragment halves
        uint32_t ph0[8], ph1[8], pl0[8], pl1[8];
        float sum0 = 0.f, sum1 = 0.f;
        #pragma unroll
        for (int j = 0; j < 8; j++) {
            float p0 = __expf(sacc[j][0] - m0n);
            float p1 = __expf(sacc[j][1] - m0n);
            float p2 = __expf(sacc[j][2] - m1n);
            float p3 = __expf(sacc[j][3] - m1n);
            sum0 += p0 + p1;
            sum1 += p2 + p3;
            __nv_bfloat16 h0, h1, l0, l1;
            split2(p0, h0, l0); split2(p1, h1, l1);
            ph0[j] = packbf(h0, h1); pl0[j] = packbf(l0, l1);
            split2(p2, h0, l0); split2(p3, h1, l1);
            ph1[j] = packbf(h0, h1); pl1[j] = packbf(l0, l1);
        }
        sum0 += __shfl_xor_sync(0xffffffffu, sum0, 1);
        sum0 += __shfl_xor_sync(0xffffffffu, sum0, 2);
        sum1 += __shfl_xor_sync(0xffffffffu, sum1, 1);
        sum1 += __shfl_xor_sync(0xffffffffu, sum1, 2);

        rsm0 = rsm0 * corr0 + sum0;
        rsm1 = rsm1 * corr1 + sum1;
        rmx0 = m0n;
        rmx1 = m1n;

        #pragma unroll
        for (int j = 0; j < 16; j++) {
            o[j][0] *= corr0; o[j][1] *= corr0;
            o[j][2] *= corr1; o[j][3] *= corr1;
        }

        // ---- O += P @ V (bf16x3, P from registers) ----
        #pragma unroll
        for (int pass = 0; pass < 3; pass++) {
            const uint32_t* a0 = (pass == 2) ? pl0 : ph0;
            const uint32_t* a1 = (pass == 2) ? pl1 : ph1;
            const __nv_bfloat16* Vb = (pass == 1) ? Vl : Vh;
            #pragma unroll
            for (int ks = 0; ks < 4; ks++) {
                const int k0 = ks * 16;
                uint32_t a[4];
                a[0] = a0[2 * ks];
                a[1] = a1[2 * ks];
                a[2] = a0[2 * ks + 1];
                a[3] = a1[2 * ks + 1];
                #pragma unroll
                for (int p = 0; p < 8; p++) {
                    uint32_t bb[4];
                    ldmx4(bb, &Vb[(16 * p + lm_r) * TPIT + k0 + lm_c]);
                    mma_bf16(o[2 * p],     a, bb[0], bb[2]);
                    mma_bf16(o[2 * p + 1], a, bb[1], bb[3]);
                }
            }
        }
    }

    // epilogue: write bf16 hi/lo split directly (input to Wo GEMM)
    float inv0 = 1.0f / rsm0;
    float inv1 = 1.0f / rsm1;
    size_t row0 = ((size_t)b * S_ + m0 + 16 * wid + g) * H_ * D_;
    size_t row1 = row0 + (size_t)8 * H_ * D_;
    #pragma unroll
    for (int j = 0; j < 16; j++) {
        int col = h * D_ + 8 * j + 2 * t;
        __nv_bfloat16 h0, h1, l0, l1;
        split2(o[j][0] * inv0, h0, l0);
        split2(o[j][1] * inv0, h1, l1);
        *(__nv_bfloat162*)&g_Ahi[row0 + col] = __halves2bfloat162(h0, h1);
        *(__nv_bfloat162*)&g_Alo[row0 + col] = __halves2bfloat162(l0, l1);
        split2(o[j][2] * inv1, h0, l0);
        split2(o[j][3] * inv1, h1, l1);
        *(__nv_bfloat162*)&g_Ahi[row1 + col] = __halves2bfloat162(h0, h1);
        *(__nv_bfloat162*)&g_Alo[row1 + col] = __halves2bfloat162(l0, l1);
    }
}

// ---------------------------------------------------------------------------
// Launch
// ---------------------------------------------------------------------------
extern "C" void kernel_launch(void* const* d_in, const int* in_sizes, int n_in,
                              void* d_out, int out_size)
{
    const float* x    = (const float*)d_in[0];
    const float* cosb = (const float*)d_in[1];
    const float* sinb = (const float*)d_in[2];
    const float* Wq   = (const float*)d_in[3];
    const float* Wk   = (const float*)d_in[4];
    const float* Wv   = (const float*)d_in[5];
    const float* Wo   = (const float*)d_in[6];
    const float* qw   = (const float*)d_in[7];
    const float* kw   = (const float*)d_in[8];
    float* out = (float*)d_out;

    float* qkv;
    cudaGetSymbolAddress((void**)&qkv, g_qkv);
    __nv_bfloat16 *Ahi, *Alo, *WqkvTh, *WqkvTl, *WoTh, *WoTl;
    __nv_bfloat16 *qhi, *qlo, *khi, *klo;
    cudaGetSymbolAddress((void**)&Ahi,    g_Ahi);
    cudaGetSymbolAddress((void**)&Alo,    g_Alo);
    cudaGetSymbolAddress((void**)&WqkvTh, g_WqkvT_hi);
    cudaGetSymbolAddress((void**)&WqkvTl, g_WqkvT_lo);
    cudaGetSymbolAddress((void**)&WoTh,   g_WoT_hi);
    cudaGetSymbolAddress((void**)&WoTl,   g_WoT_lo);
    cudaGetSymbolAddress((void**)&qhi,    g_qhi);
    cudaGetSymbolAddress((void**)&qlo,    g_qlo);
    cudaGetSymbolAddress((void**)&khi,    g_khi);
    cudaGetSymbolAddress((void**)&klo,    g_klo);

    const int M = B_ * S_;
    const int n4x = M * HID_ / 4;

    cudaFuncSetAttribute(mm_mma_kernel,
                         cudaFuncAttributeMaxDynamicSharedMemorySize, MM_SMEM);
    cudaFuncSetAttribute(attn_mma_kernel,
                         cudaFuncAttributeMaxDynamicSharedMemorySize, ATT_SMEM);

    // Split input + weights (Wq/Wk/Wv concatenated along N into one buffer)
    split_kernel<<<4096, 256>>>(x, Ahi, Alo, n4x);
    split_T_kernel<<<dim3((H_ * D_) / 32, HID_ / 32), dim3(32, 8)>>>(
        Wq, WqkvTh, WqkvTl, HID_, H_ * D_);
    split_T_kernel<<<dim3((KV_ * D_) / 32, HID_ / 32), dim3(32, 8)>>>(
        Wk, WqkvTh + (size_t)KOFF * HID_, WqkvTl + (size_t)KOFF * HID_, HID_, KV_ * D_);
    split_T_kernel<<<dim3((KV_ * D_) / 32, HID_ / 32), dim3(32, 8)>>>(
        Wv, WqkvTh + (size_t)VOFF * HID_, WqkvTl + (size_t)VOFF * HID_, HID_, KV_ * D_);
    split_T_kernel<<<dim3(HID_ / 32, (H_ * D_) / 32), dim3(32, 8)>>>(
        Wo, WoTh, WoTl, H_ * D_, HID_);

    // Fused QKV projection (one GEMM, N=3072)
    mm_mma_kernel<<<dim3(NQKV / 128, M / 128), 256, MM_SMEM>>>(
        Ahi, Alo, WqkvTh, WqkvTl, qkv, M, NQKV, HID_);

    // RMSNorm + RoPE -> bf16 hi/lo
    norm_rope_split_kernel<<<(B_ * S_ * H_) / 8, 256>>>(
        qkv, NQKV, cosb, sinb, qw, qhi, qlo, H_);
    norm_rope_split_kernel<<<(B_ * S_ * KV_) / 8, 256>>>(
        qkv + KOFF, NQKV, cosb, sinb, kw, khi, klo, KV_);

    // V transpose + split
    vt_split_kernel<<<dim3(S_ / 32, D_ / 32, B_ * KV_), dim3(32, 8)>>>();

    // Attention (R7 config; writes bf16 hi/lo split directly into Ahi/Alo)
    attn_mma_kernel<<<dim3(S_ / 128, H_, B_), 256, ATT_SMEM>>>();

    // Output projection
    mm_mma_kernel<<<dim3(HID_ / 128, M / 128), 256, MM_SMEM>>>(
        Ahi, Alo, WoTh, WoTl, out, M, HID_, HID_);
}

// round 14
// speedup vs baseline: 1.0418x; 1.0029x over previous
#include <cuda_runtime.h>
#include <cuda_bf16.h>
#include <cstdint>
#include <math.h>

// Problem constants
namespace {
constexpr int B_   = 4;
constexpr int S_   = 2048;
constexpr int HID_ = 2048;
constexpr int H_   = 16;
constexpr int KV_  = 4;
constexpr int D_   = 128;
constexpr int G_   = H_ / KV_;
constexpr float EPS_   = 1e-6f;
constexpr float SCALE_ = 0.088388347648318447f; // 128^-0.5
constexpr int NQKV  = H_ * D_ + 2 * KV_ * D_;   // 3072
constexpr int KOFF  = H_ * D_;                  // 2048
constexpr int VOFF  = H_ * D_ + KV_ * D_;       // 2560
}

// ---------------------------------------------------------------------------
// Scratch — device globals (no cudaMalloc allowed)
// ---------------------------------------------------------------------------
__device__ float g_qkv[(size_t)B_ * S_ * NQKV];   // fused qkv projection fp32

__device__ __nv_bfloat16 g_Ahi[(size_t)B_ * S_ * HID_];
__device__ __nv_bfloat16 g_Alo[(size_t)B_ * S_ * HID_];
__device__ __nv_bfloat16 g_WqkvT_hi[(size_t)NQKV * HID_];
__device__ __nv_bfloat16 g_WqkvT_lo[(size_t)NQKV * HID_];
__device__ __nv_bfloat16 g_WoT_hi[(size_t)HID_ * H_ * D_];
__device__ __nv_bfloat16 g_WoT_lo[(size_t)HID_ * H_ * D_];

__device__ __nv_bfloat16 g_qhi[(size_t)B_ * S_ * H_ * D_];
__device__ __nv_bfloat16 g_qlo[(size_t)B_ * S_ * H_ * D_];
__device__ __nv_bfloat16 g_khi[(size_t)B_ * S_ * KV_ * D_];
__device__ __nv_bfloat16 g_klo[(size_t)B_ * S_ * KV_ * D_];
__device__ __nv_bfloat16 g_vthi[(size_t)B_ * KV_ * D_ * S_];  // [b][kv][d][s]
__device__ __nv_bfloat16 g_vtlo[(size_t)B_ * KV_ * D_ * S_];

// ---------------------------------------------------------------------------
// Helpers
// ---------------------------------------------------------------------------
__device__ __forceinline__ void mma_bf16(float* c, const uint32_t* a,
                                         uint32_t b0, uint32_t b1) {
    asm volatile(
        "mma.sync.aligned.m16n8k16.row.col.f32.bf16.bf16.f32 "
        "{%0,%1,%2,%3}, {%4,%5,%6,%7}, {%8,%9}, {%0,%1,%2,%3};"
        : "+f"(c[0]), "+f"(c[1]), "+f"(c[2]), "+f"(c[3])
        : "r"(a[0]), "r"(a[1]), "r"(a[2]), "r"(a[3]), "r"(b0), "r"(b1));
}

// Warp-collective ldmatrix x4: each thread passes its own row address.
__device__ __forceinline__ void ldmx4(uint32_t* r, const __nv_bfloat16* p) {
    uint32_t a = (uint32_t)__cvta_generic_to_shared(p);
    asm volatile("ldmatrix.sync.aligned.m8n8.x4.shared.b16 {%0,%1,%2,%3}, [%4];"
        : "=r"(r[0]), "=r"(r[1]), "=r"(r[2]), "=r"(r[3]) : "r"(a));
}

__device__ __forceinline__ void split2(float v, __nv_bfloat16& h, __nv_bfloat16& l) {
    h = __float2bfloat16(v);
    l = __float2bfloat16(v - __bfloat162float(h));
}

__device__ __forceinline__ uint32_t packbf(__nv_bfloat16 a, __nv_bfloat16 b) {
    __nv_bfloat162 v = __halves2bfloat162(a, b);
    return *(uint32_t*)&v;
}

__device__ __forceinline__ void cp16(void* s, const void* g) {
    uint32_t sa = (uint32_t)__cvta_generic_to_shared(s);
    asm volatile("cp.async.ca.shared.global [%0], [%1], 16;" :: "r"(sa), "l"(g));
}
#define CP_COMMIT() asm volatile("cp.async.commit_group;" ::: "memory")
#define CP_WAIT(n)  asm volatile("cp.async.wait_group %0;" :: "n"(n) : "memory")

// ---------------------------------------------------------------------------
// Input split: fp32 -> bf16 hi/lo
// ---------------------------------------------------------------------------
__global__ __launch_bounds__(256) void split_kernel(
    const float* __restrict__ X, __nv_bfloat16* __restrict__ hi,
    __nv_bfloat16* __restrict__ lo, int n4)
{
    int i = blockIdx.x * blockDim.x + threadIdx.x;
    int stride = gridDim.x * blockDim.x;
    for (; i < n4; i += stride) {
        float4 v = ((const float4*)X)[i];
        __nv_bfloat16 h0, h1, h2, h3, l0, l1, l2, l3;
        split2(v.x, h0, l0); split2(v.y, h1, l1);
        split2(v.z, h2, l2); split2(v.w, h3, l3);
        ((__nv_bfloat162*)hi)[i * 2]     = __halves2bfloat162(h0, h1);
        ((__nv_bfloat162*)hi)[i * 2 + 1] = __halves2bfloat162(h2, h3);
        ((__nv_bfloat162*)lo)[i * 2]     = __halves2bfloat162(l0, l1);
        ((__nv_bfloat162*)lo)[i * 2 + 1] = __halves2bfloat162(l2, l3);
    }
}

// ---------------------------------------------------------------------------
// Fused weight split: ALL four weights transposed+split in one launch.
// Tile ranges (32x32 tiles):
//   Wq:  tiles [0,      4096)   (Nd=2048 -> 64 n-tiles, Kd... source [2048,2048])
//   Wk:  tiles [4096,   5120)   (source [2048,512])
//   Wv:  tiles [5120,   6144)
//   Wo:  tiles [6144,  10240)   (source [2048,2048])
// Each tile: source W[Kd,Nd] block (bk,bn) -> dest [Nd,Kd] at given base.
// ---------------------------------------------------------------------------
__global__ __launch_bounds__(256) void split_weights_kernel(
    const float* __restrict__ Wq, const float* __restrict__ Wk,
    const float* __restrict__ Wv, const float* __restrict__ Wo,
    __nv_bfloat16* __restrict__ WqkvTh, __nv_bfloat16* __restrict__ WqkvTl,
    __nv_bfloat16* __restrict__ WoTh,   __nv_bfloat16* __restrict__ WoTl)
{
    __shared__ float tbuf[32][33];
    const int tx = threadIdx.x, ty = threadIdx.y;
    int tile = blockIdx.x;

    const float* W;
    __nv_bfloat16 *dh, *dl;
    int Nd, ntile_n;           // source cols, tiles along n
    // dest row offset within its buffer (in units of rows of length Kd=2048)
    int dest_row_off;

    if (tile < 4096) {                       // Wq: Nd=2048, 64 n-tiles x 64 k-tiles
        W = Wq; dh = WqkvTh; dl = WqkvTl;
        Nd = H_ * D_; ntile_n = Nd / 32; dest_row_off = 0;
    } else if (tile < 5120) {                // Wk: Nd=512, 16 n-tiles x 64 k-tiles
        tile -= 4096;
        W = Wk; dh = WqkvTh; dl = WqkvTl;
        Nd = KV_ * D_; ntile_n = Nd / 32; dest_row_off = KOFF;
    } else if (tile < 6144) {                // Wv
        tile -= 5120;
        W = Wv; dh = WqkvTh; dl = WqkvTl;
        Nd = KV_ * D_; ntile_n = Nd / 32; dest_row_off = VOFF;
    } else {                                 // Wo: Nd=2048
        tile -= 6144;
        W = Wo; dh = WoTh; dl = WoTl;
        Nd = HID_; ntile_n = Nd / 32; dest_row_off = 0;
    }
    const int Kd = 2048;                     // all sources have 2048 rows
    const int bn = (tile % ntile_n) * 32;
    const int bk = (tile / ntile_n) * 32;

    #pragma unroll
    for (int i = ty; i < 32; i += 8)
        tbuf[i][tx] = W[(size_t)(bk + i) * Nd + bn + tx];
    __syncthreads();
    #pragma unroll
    for (int i = ty; i < 32; i += 8) {
        float v = tbuf[tx][i];               // = W[bk+tx][bn+i]
        __nv_bfloat16 h, l;
        split2(v, h, l);
        size_t o = (size_t)(dest_row_off + bn + i) * Kd + bk + tx;
        dh[o] = h;
        dl[o] = l;
    }
}

// V fp32 (inside g_qkv, row stride NQKV) -> Vt hi/lo bf16 [b,kv,d,s]
__global__ __launch_bounds__(256) void vt_split_kernel()
{
    __shared__ float t[32][33];
    const int b  = blockIdx.z / KV_;
    const int kv = blockIdx.z % KV_;
    const int s0 = blockIdx.x * 32;
    const int d0 = blockIdx.y * 32;
    const int tx = threadIdx.x, ty = threadIdx.y;
    #pragma unroll
    for (int i = ty; i < 32; i += 8)
        t[i][tx] = g_qkv[((size_t)b * S_ + s0 + i) * NQKV + VOFF + kv * D_ + d0 + tx];
    __syncthreads();
    #pragma unroll
    for (int i = ty; i < 32; i += 8) {
        float v = t[tx][i];
        __nv_bfloat16 h, l;
        split2(v, h, l);
        size_t o = (((size_t)b * KV_ + kv) * D_ + d0 + i) * S_ + s0 + tx;
        g_vthi[o] = h;
        g_vtlo[o] = l;
    }
}

// ---------------------------------------------------------------------------
// Pipelined mma.sync GEMM: C = A @ B^T, bf16x3 (pass-major stages).
// CTA 128x128, 8 warps, 2-stage cp.async double buffer; ldmatrix fragments.
// 73728 B dyn smem -> 2 CTAs/SM.  (R7 config — proven optimal across probes)
// ---------------------------------------------------------------------------
constexpr int MMP   = 72;
constexpr int MMT   = 128 * MMP;        // 9216 bf16 per tile
constexpr int MMSTG = 2 * MMT;          // A + B tile
constexpr int MM_SMEM = 2 * MMSTG * 2;  // 73728 bytes

__global__ __launch_bounds__(256, 2) void mm_mma_kernel(
    const __nv_bfloat16* __restrict__ Ahi, const __nv_bfloat16* __restrict__ Alo,
    const __nv_bfloat16* __restrict__ Bhi, const __nv_bfloat16* __restrict__ Blo,
    float* __restrict__ C, int M, int N, int K)
{
    extern __shared__ char smc[];
    __nv_bfloat16* bufs = (__nv_bfloat16*)smc;   // 2 stages of MMSTG

    const int tid  = threadIdx.x;
    const int wid  = tid >> 5;
    const int lane = tid & 31;
    const int g    = lane >> 2;
    const int t    = lane & 3;
    const int wr   = wid >> 1;
    const int wc   = wid & 1;
    const int m0 = blockIdx.y * 128;
    const int n0 = blockIdx.x * 128;

    const int lm_r = lane & 15;
    const int lm_c = (lane >> 4) * 8;

    float acc[2][8][4];
    #pragma unroll
    for (int mb = 0; mb < 2; mb++)
        #pragma unroll
        for (int nb = 0; nb < 8; nb++)
            #pragma unroll
            for (int e = 0; e < 4; e++) acc[mb][nb][e] = 0.f;

    const int cpp   = K / 64;
    const int total = 3 * cpp;

    auto issue = [&](int s) {
        const int pass = s / cpp;
        const int kc   = (s - pass * cpp) * 64;
        const __nv_bfloat16* Ap = (pass == 2) ? Alo : Ahi;
        const __nv_bfloat16* Bp = (pass == 1) ? Blo : Bhi;
        __nv_bfloat16* st = bufs + (s & 1) * MMSTG;
        #pragma unroll
        for (int i = 0; i < 4; i++) {
            int idx = tid + i * 256;
            int row = idx >> 3;
            int c   = (idx & 7) * 8;
            cp16(st + row * MMP + c,       &Ap[(size_t)(m0 + row) * K + kc + c]);
            cp16(st + MMT + row * MMP + c, &Bp[(size_t)(n0 + row) * K + kc + c]);
        }
        CP_COMMIT();
    };

    issue(0);

    for (int s = 0; s < total; ++s) {
        if (s + 1 < total) { issue(s + 1); CP_WAIT(1); }
        else               { CP_WAIT(0); }
        __syncthreads();

        const __nv_bfloat16* As = bufs + (s & 1) * MMSTG;
        const __nv_bfloat16* Bs = As + MMT;
        #pragma unroll
        for (int ks = 0; ks < 4; ks++) {
            const int k0 = ks * 16;
            uint32_t a[2][4];
            #pragma unroll
            for (int mb = 0; mb < 2; mb++)
                ldmx4(a[mb], &As[(32 * wr + 16 * mb + lm_r) * MMP + k0 + lm_c]);
            uint32_t bb[4][4];
            #pragma unroll
            for (int p = 0; p < 4; p++)
                ldmx4(bb[p], &Bs[(64 * wc + 16 * p + lm_r) * MMP + k0 + lm_c]);
            #pragma unroll
            for (int p = 0; p < 4; p++) {
                mma_bf16(acc[0][2 * p],     a[0], bb[p][0], bb[p][2]);
                mma_bf16(acc[0][2 * p + 1], a[0], bb[p][1], bb[p][3]);
                mma_bf16(acc[1][2 * p],     a[1], bb[p][0], bb[p][2]);
                mma_bf16(acc[1][2 * p + 1], a[1], bb[p][1], bb[p][3]);
            }
        }
        __syncthreads();
    }

    #pragma unroll
    for (int mb = 0; mb < 2; mb++) {
        int row0 = m0 + 32 * wr + 16 * mb + g;
        #pragma unroll
        for (int nb = 0; nb < 8; nb++) {
            int col = n0 + 64 * wc + 8 * nb + 2 * t;
            *(float2*)&C[(size_t)row0 * N + col] =
                make_float2(acc[mb][nb][0], acc[mb][nb][1]);
            *(float2*)&C[(size_t)(row0 + 8) * N + col] =
                make_float2(acc[mb][nb][2], acc[mb][nb][3]);
        }
    }
}

// ---------------------------------------------------------------------------
// Fused RMSNorm + RoPE -> bf16 hi/lo, Q and K in ONE launch.
// Blocks [0, QBLK) handle q rows; blocks [QBLK, QBLK+KBLK) handle k rows.
// ---------------------------------------------------------------------------
constexpr int NR_QBLK = (B_ * S_ * H_) / 8;    // 16384
constexpr int NR_KBLK = (B_ * S_ * KV_) / 8;   // 4096

__global__ __launch_bounds__(256) void norm_rope_split_kernel(
    const float* __restrict__ qkv,
    const float* __restrict__ cosb, const float* __restrict__ sinb,
    const float* __restrict__ qw, const float* __restrict__ kw,
    __nv_bfloat16* __restrict__ qhi, __nv_bfloat16* __restrict__ qlo,
    __nv_bfloat16* __restrict__ khi, __nv_bfloat16* __restrict__ klo)
{
    const bool is_q = blockIdx.x < NR_QBLK;
    const int blk   = is_q ? blockIdx.x : blockIdx.x - NR_QBLK;
    const int nheads = is_q ? H_ : KV_;
    const float* x  = is_q ? qkv : qkv + KOFF;
    const float* w  = is_q ? qw : kw;
    __nv_bfloat16* hi = is_q ? qhi : khi;
    __nv_bfloat16* lo = is_q ? qlo : klo;

    const int warp = (blk * 256 + (int)threadIdx.x) >> 5;
    const int lane = threadIdx.x & 31;
    const int local = warp - blk * 8 + blk * 8;  // == warp (kept simple)
    (void)local;

    const int bs   = warp / nheads;
    const int head = warp - bs * nheads;
    const int s    = bs % S_;

    const float* row = x + (size_t)bs * NQKV + (size_t)head * D_;
    size_t obase = (size_t)bs * nheads * D_ + (size_t)head * D_;

    float x0 = row[lane];
    float x1 = row[lane + 32];
    float x2 = row[lane + 64];
    float x3 = row[lane + 96];

    float ss = x0 * x0 + x1 * x1 + x2 * x2 + x3 * x3;
    #pragma unroll
    for (int o = 16; o > 0; o >>= 1) ss += __shfl_xor_sync(0xffffffffu, ss, o);
    float inv = rsqrtf(ss * (1.0f / (float)D_) + EPS_);

    float n0 = x0 * inv * w[lane];
    float n1 = x1 * inv * w[lane + 32];
    float n2 = x2 * inv * w[lane + 64];
    float n3 = x3 * inv * w[lane + 96];

    const float* cr = cosb + (size_t)s * D_;
    const float* sr = sinb + (size_t)s * D_;

    float r0 = n0 * cr[lane]      - n2 * sr[lane];
    float r1 = n1 * cr[lane + 32] - n3 * sr[lane + 32];
    float r2 = n2 * cr[lane + 64] + n0 * sr[lane + 64];
    float r3 = n3 * cr[lane + 96] + n1 * sr[lane + 96];

    __nv_bfloat16 h, l;
    split2(r0, h, l); hi[obase + lane]      = h; lo[obase + lane]      = l;
    split2(r1, h, l); hi[obase + lane + 32] = h; lo[obase + lane + 32] = l;
    split2(r2, h, l); hi[obase + lane + 64] = h; lo[obase + lane + 64] = l;
    split2(r3, h, l); hi[obase + lane + 96] = h; lo[obase + lane + 96] = l;
}

// ---------------------------------------------------------------------------
// Flash attention, bf16x3, BM=128, warp-owns-rows layout (R7 — proven optimal).
// ---------------------------------------------------------------------------
constexpr int APIT = 136;
constexpr int TPIT = 72;
constexpr int AQSZ = 128 * APIT;   // Q tile (128 rows)
constexpr int AKSZ = 64 * APIT;    // K tile (64 tokens)
constexpr int AVSZ = 128 * TPIT;   // Vt tile (128 d x 64 tokens)
constexpr int ATT_SMEM = (2 * AQSZ + 2 * AKSZ + 2 * AVSZ) * 2;  // 141312 B

__global__ __launch_bounds__(256) void attn_mma_kernel()
{
    extern __shared__ char smc[];
    __nv_bfloat16* Qh = (__nv_bfloat16*)smc;
    __nv_bfloat16* Ql = Qh + AQSZ;
    __nv_bfloat16* Kh = Ql + AQSZ;
    __nv_bfloat16* Kl = Kh + AKSZ;
    __nv_bfloat16* Vh = Kl + AKSZ;
    __nv_bfloat16* Vl = Vh + AVSZ;

    const int tid  = threadIdx.x;
    const int wid  = tid >> 5;
    const int lane = tid & 31;
    const int g    = lane >> 2;
    const int t    = lane & 3;

    const int m0  = blockIdx.x * 128;
    const int h   = blockIdx.y;
    const int b   = blockIdx.z;
    const int kvh = h / G_;

    const int lm_r = lane & 15;
    const int lm_c = (lane >> 4) * 8;

    // stage Q (128 rows x 128 d, hi+lo)
    {
        const __nv_bfloat16* qh = g_qhi + (((size_t)b * S_ + m0) * H_ + h) * D_;
        const __nv_bfloat16* ql = g_qlo + (((size_t)b * S_ + m0) * H_ + h) * D_;
        #pragma unroll
        for (int i = 0; i < 8; i++) {
            int idx = tid + i * 256;
            int r   = idx >> 4;
            int c   = (idx & 15) * 8;
            *(uint4*)&Qh[r * APIT + c] = *(const uint4*)&qh[(size_t)r * H_ * D_ + c];
            *(uint4*)&Ql[r * APIT + c] = *(const uint4*)&ql[(size_t)r * H_ * D_ + c];
        }
    }

    float o[16][4];
    #pragma unroll
    for (int j = 0; j < 16; j++)
        #pragma unroll
        for (int e = 0; e < 4; e++) o[j][e] = 0.f;
    float rmx0 = -3.0e38f, rmx1 = -3.0e38f;
    float rsm0 = 0.f, rsm1 = 0.f;

    const __nv_bfloat16* khb = g_khi + ((size_t)b * S_ * KV_ + kvh) * D_;
    const __nv_bfloat16* klb = g_klo + ((size_t)b * S_ * KV_ + kvh) * D_;
    const __nv_bfloat16* vhb = g_vthi + ((size_t)b * KV_ + kvh) * D_ * S_;
    const __nv_bfloat16* vlb = g_vtlo + ((size_t)b * KV_ + kvh) * D_ * S_;

    for (int t0 = 0; t0 < S_; t0 += 64) {
        __syncthreads();   // previous tile's V reads done before overwrite
        #pragma unroll
        for (int i = 0; i < 4; i++) {
            int idx = tid + i * 256;
            int r   = idx >> 4;
            int c   = (idx & 15) * 8;
            size_t go = (size_t)(t0 + r) * KV_ * D_ + c;
            *(uint4*)&Kh[r * APIT + c] = *(const uint4*)&khb[go];
            *(uint4*)&Kl[r * APIT + c] = *(const uint4*)&klb[go];
            int d  = idx >> 3;
            int c2 = (idx & 7) * 8;
            size_t gv = (size_t)d * S_ + t0 + c2;
            *(uint4*)&Vh[d * TPIT + c2] = *(const uint4*)&vhb[gv];
            *(uint4*)&Vl[d * TPIT + c2] = *(const uint4*)&vlb[gv];
        }
        __syncthreads();

        // ---- S = Q @ K^T (bf16x3, ldmatrix) ----
        float sacc[8][4];
        #pragma unroll
        for (int j = 0; j < 8; j++)
            #pragma unroll
            for (int e = 0; e < 4; e++) sacc[j][e] = 0.f;

        #pragma unroll
        for (int pass = 0; pass < 3; pass++) {
            const __nv_bfloat16* Aq = (pass == 2) ? Ql : Qh;
            const __nv_bfloat16* Bk = (pass == 1) ? Kl : Kh;
            #pragma unroll
            for (int ks = 0; ks < 8; ks++) {
                const int k0 = ks * 16;
                uint32_t a[4];
                ldmx4(a, &Aq[(16 * wid + lm_r) * APIT + k0 + lm_c]);
                uint32_t bb[4][4];
                #pragma unroll
                for (int p = 0; p < 4; p++)
                    ldmx4(bb[p], &Bk[(16 * p + lm_r) * APIT + k0 + lm_c]);
                #pragma unroll
                for (int p = 0; p < 4; p++) {
                    mma_bf16(sacc[2 * p],     a, bb[p][0], bb[p][2]);
                    mma_bf16(sacc[2 * p + 1], a, bb[p][1], bb[p][3]);
                }
            }
        }

        // ---- in-warp online softmax ----
        float mx0 = -3.0e38f, mx1 = -3.0e38f;
        #pragma unroll
        for (int j = 0; j < 8; j++) {
            #pragma unroll
            for (int e = 0; e < 4; e++) sacc[j][e] *= SCALE_;
            mx0 = fmaxf(mx0, fmaxf(sacc[j][0], sacc[j][1]));
            mx1 = fmaxf(mx1, fmaxf(sacc[j][2], sacc[j][3]));
        }
        mx0 = fmaxf(mx0, __shfl_xor_sync(0xffffffffu, mx0, 1));
        mx0 = fmaxf(mx0, __shfl_xor_sync(0xffffffffu, mx0, 2));
        mx1 = fmaxf(mx1, __shfl_xor_sync(0xffffffffu, mx1, 1));
        mx1 = fmaxf(mx1, __shfl_xor_sync(0xffffffffu, mx1, 2));

        float m0n = fmaxf(rmx0, mx0);
        float m1n = fmaxf(rmx1, mx1);
        float corr0 = __expf(rmx0 - m0n);
        float corr1 = __expf(rmx1 - m1n);

        // exp + register split of P into hi/lo A-fragment halves
        uint32_t ph0[8], ph1[8], pl0[8], pl1[8];
        float sum0 = 0.f, sum1 = 0.f;
        #pragma unroll
        for (int j = 0; j < 8; j++) {
            float p0 = __expf(sacc[j][0] - m0n);
            float p1 = __expf(sacc[j][1] - m0n);
            float p2 = __expf(sacc[j][2] - m1n);
            float p3 = __expf(sacc[j][3] - m1n);
            sum0 += p0 + p1;
            sum1 += p2 + p3;
            __nv_bfloat16 h0, h1, l0, l1;
            split2(p0, h0, l0); split2(p1, h1, l1);
            ph0[j] = packbf(h0, h1); pl0[j] = packbf(l0, l1);
            split2(p2, h0, l0); split2(p3, h1, l1);
            ph1[j] = packbf(h0, h1); pl1[j] = packbf(l0, l1);
        }
        sum0 += __shfl_xor_sync(0xffffffffu, sum0, 1);
        sum0 += __shfl_xor_sync(0xffffffffu, sum0, 2);
        sum1 += __shfl_xor_sync(0xffffffffu, sum1, 1);
        sum1 += __shfl_xor_sync(0xffffffffu, sum1, 2);

        rsm0 = rsm0 * corr0 + sum0;
        rsm1 = rsm1 * corr1 + sum1;
        rmx0 = m0n;
        rmx1 = m1n;

        #pragma unroll
        for (int j = 0; j < 16; j++) {
            o[j][0] *= corr0; o[j][1] *= corr0;
            o[j][2] *= corr1; o[j][3] *= corr1;
        }

        // ---- O += P @ V (bf16x3, P from registers) ----
        #pragma unroll
        for (int pass = 0; pass < 3; pass++) {
            const uint32_t* a0 = (pass == 2) ? pl0 : ph0;
            const uint32_t* a1 = (pass == 2) ? pl1 : ph1;
            const __nv_bfloat16* Vb = (pass == 1) ? Vl : Vh;
            #pragma unroll
            for (int ks = 0; ks < 4; ks++) {
                const int k0 = ks * 16;
                uint32_t a[4];
                a[0] = a0[2 * ks];
                a[1] = a1[2 * ks];
                a[2] = a0[2 * ks + 1];
                a[3] = a1[2 * ks + 1];
                #pragma unroll
                for (int p = 0; p < 8; p++) {
                    uint32_t bb[4];
                    ldmx4(bb, &Vb[(16 * p + lm_r) * TPIT + k0 + lm_c]);
                    mma_bf16(o[2 * p],     a, bb[0], bb[2]);
                    mma_bf16(o[2 * p + 1], a, bb[1], bb[3]);
                }
            }
        }
    }

    // epilogue: write bf16 hi/lo split directly (input to Wo GEMM)
    float inv0 = 1.0f / rsm0;
    float inv1 = 1.0f / rsm1;
    size_t row0 = ((size_t)b * S_ + m0 + 16 * wid + g) * H_ * D_;
    size_t row1 = row0 + (size_t)8 * H_ * D_;
    #pragma unroll
    for (int j = 0; j < 16; j++) {
        int col = h * D_ + 8 * j + 2 * t;
        __nv_bfloat16 h0, h1, l0, l1;
        split2(o[j][0] * inv0, h0, l0);
        split2(o[j][1] * inv0, h1, l1);
        *(__nv_bfloat162*)&g_Ahi[row0 + col] = __halves2bfloat162(h0, h1);
        *(__nv_bfloat162*)&g_Alo[row0 + col] = __halves2bfloat162(l0, l1);
        split2(o[j][2] * inv1, h0, l0);
        split2(o[j][3] * inv1, h1, l1);
        *(__nv_bfloat162*)&g_Ahi[row1 + col] = __halves2bfloat162(h0, h1);
        *(__nv_bfloat162*)&g_Alo[row1 + col] = __halves2bfloat162(l0, l1);
    }
}

// ---------------------------------------------------------------------------
// Launch
// ---------------------------------------------------------------------------
extern "C" void kernel_launch(void* const* d_in, const int* in_sizes, int n_in,
                              void* d_out, int out_size)
{
    const float* x    = (const float*)d_in[0];
    const float* cosb = (const float*)d_in[1];
    const float* sinb = (const float*)d_in[2];
    const float* Wq   = (const float*)d_in[3];
    const float* Wk   = (const float*)d_in[4];
    const float* Wv   = (const float*)d_in[5];
    const float* Wo   = (const float*)d_in[6];
    const float* qw   = (const float*)d_in[7];
    const float* kw   = (const float*)d_in[8];
    float* out = (float*)d_out;

    float* qkv;
    cudaGetSymbolAddress((void**)&qkv, g_qkv);
    __nv_bfloat16 *Ahi, *Alo, *WqkvTh, *WqkvTl, *WoTh, *WoTl;
    __nv_bfloat16 *qhi, *qlo, *khi, *klo;
    cudaGetSymbolAddress((void**)&Ahi,    g_Ahi);
    cudaGetSymbolAddress((void**)&Alo,    g_Alo);
    cudaGetSymbolAddress((void**)&WqkvTh, g_WqkvT_hi);
    cudaGetSymbolAddress((void**)&WqkvTl, g_WqkvT_lo);
    cudaGetSymbolAddress((void**)&WoTh,   g_WoT_hi);
    cudaGetSymbolAddress((void**)&WoTl,   g_WoT_lo);
    cudaGetSymbolAddress((void**)&qhi,    g_qhi);
    cudaGetSymbolAddress((void**)&qlo,    g_qlo);
    cudaGetSymbolAddress((void**)&khi,    g_khi);
    cudaGetSymbolAddress((void**)&klo,    g_klo);

    const int M = B_ * S_;
    const int n4x = M * HID_ / 4;

    cudaFuncSetAttribute(mm_mma_kernel,
                         cudaFuncAttributeMaxDynamicSharedMemorySize, MM_SMEM);
    cudaFuncSetAttribute(attn_mma_kernel,
                         cudaFuncAttributeMaxDynamicSharedMemorySize, ATT_SMEM);

    // Split input (x) and ALL weights (one fused launch)
    split_kernel<<<4096, 256>>>(x, Ahi, Alo, n4x);
    split_weights_kernel<<<10240, dim3(32, 8)>>>(
        Wq, Wk, Wv, Wo, WqkvTh, WqkvTl, WoTh, WoTl);

    // Fused QKV projection (one GEMM, N=3072)
    mm_mma_kernel<<<dim3(NQKV / 128, M / 128), 256, MM_SMEM>>>(
        Ahi, Alo, WqkvTh, WqkvTl, qkv, M, NQKV, HID_);

    // RMSNorm + RoPE for Q and K in one launch
    norm_rope_split_kernel<<<NR_QBLK + NR_KBLK, 256>>>(
        qkv, cosb, sinb, qw, kw, qhi, qlo, khi, klo);

    // V transpose + split
    vt_split_kernel<<<dim3(S_ / 32, D_ / 32, B_ * KV_), dim3(32, 8)>>>();

    // Attention (R7 config; writes bf16 hi/lo split directly into Ahi/Alo)
    attn_mma_kernel<<<dim3(S_ / 128, H_, B_), 256, ATT_SMEM>>>();

    // Output projection
    mm_mma_kernel<<<dim3(HID_ / 128, M / 128), 256, MM_SMEM>>>(
        Ahi, Alo, WoTh, WoTl, out, M, HID_, HID_);
}

// round 15
// speedup vs baseline: 1.0511x; 1.0089x over previous
#include <cuda_runtime.h>
#include <cuda_bf16.h>
#include <cstdint>
#include <math.h>

// Problem constants
namespace {
constexpr int B_   = 4;
constexpr int S_   = 2048;
constexpr int HID_ = 2048;
constexpr int H_   = 16;
constexpr int KV_  = 4;
constexpr int D_   = 128;
constexpr int G_   = H_ / KV_;
constexpr float EPS_   = 1e-6f;
constexpr float SCALE_ = 0.088388347648318447f; // 128^-0.5
constexpr int NQKV  = H_ * D_ + 2 * KV_ * D_;   // 3072
constexpr int KOFF  = H_ * D_;                  // 2048
constexpr int VOFF  = H_ * D_ + KV_ * D_;       // 2560
}

// ---------------------------------------------------------------------------
// Scratch — device globals (no cudaMalloc allowed)
// ---------------------------------------------------------------------------
__device__ float g_qkv[(size_t)B_ * S_ * NQKV];   // fused qkv projection fp32

__device__ __nv_bfloat16 g_Ahi[(size_t)B_ * S_ * HID_];
__device__ __nv_bfloat16 g_Alo[(size_t)B_ * S_ * HID_];
__device__ __nv_bfloat16 g_WqkvT_hi[(size_t)NQKV * HID_];
__device__ __nv_bfloat16 g_WqkvT_lo[(size_t)NQKV * HID_];
__device__ __nv_bfloat16 g_WoT_hi[(size_t)HID_ * H_ * D_];
__device__ __nv_bfloat16 g_WoT_lo[(size_t)HID_ * H_ * D_];

__device__ __nv_bfloat16 g_qhi[(size_t)B_ * S_ * H_ * D_];
__device__ __nv_bfloat16 g_qlo[(size_t)B_ * S_ * H_ * D_];
__device__ __nv_bfloat16 g_khi[(size_t)B_ * S_ * KV_ * D_];
__device__ __nv_bfloat16 g_klo[(size_t)B_ * S_ * KV_ * D_];
__device__ __nv_bfloat16 g_vthi[(size_t)B_ * KV_ * D_ * S_];  // [b][kv][d][s]
__device__ __nv_bfloat16 g_vtlo[(size_t)B_ * KV_ * D_ * S_];

// ---------------------------------------------------------------------------
// Helpers
// ---------------------------------------------------------------------------
__device__ __forceinline__ void mma_bf16(float* c, const uint32_t* a,
                                         uint32_t b0, uint32_t b1) {
    asm volatile(
        "mma.sync.aligned.m16n8k16.row.col.f32.bf16.bf16.f32 "
        "{%0,%1,%2,%3}, {%4,%5,%6,%7}, {%8,%9}, {%0,%1,%2,%3};"
        : "+f"(c[0]), "+f"(c[1]), "+f"(c[2]), "+f"(c[3])
        : "r"(a[0]), "r"(a[1]), "r"(a[2]), "r"(a[3]), "r"(b0), "r"(b1));
}

// Warp-collective ldmatrix x4: each thread passes its own row address.
__device__ __forceinline__ void ldmx4(uint32_t* r, const __nv_bfloat16* p) {
    uint32_t a = (uint32_t)__cvta_generic_to_shared(p);
    asm volatile("ldmatrix.sync.aligned.m8n8.x4.shared.b16 {%0,%1,%2,%3}, [%4];"
        : "=r"(r[0]), "=r"(r[1]), "=r"(r[2]), "=r"(r[3]) : "r"(a));
}

__device__ __forceinline__ void split2(float v, __nv_bfloat16& h, __nv_bfloat16& l) {
    h = __float2bfloat16(v);
    l = __float2bfloat16(v - __bfloat162float(h));
}

__device__ __forceinline__ uint32_t packbf(__nv_bfloat16 a, __nv_bfloat16 b) {
    __nv_bfloat162 v = __halves2bfloat162(a, b);
    return *(uint32_t*)&v;
}

__device__ __forceinline__ void cp16(void* s, const void* g) {
    uint32_t sa = (uint32_t)__cvta_generic_to_shared(s);
    asm volatile("cp.async.ca.shared.global [%0], [%1], 16;" :: "r"(sa), "l"(g));
}
#define CP_COMMIT() asm volatile("cp.async.commit_group;" ::: "memory")
#define CP_WAIT(n)  asm volatile("cp.async.wait_group %0;" :: "n"(n) : "memory")

// ---------------------------------------------------------------------------
// Fused prep kernel: input split + all 4 weight transposed splits.
// Block ranges (256 threads as dim(32,8)):
//   [0, 4096)       : x fp32 -> Ahi/Alo (grid-strided float4)
//   [4096, 8192)    : Wq tiles (4096)
//   [8192, 9216)    : Wk tiles (1024)
//   [9216, 10240)   : Wv tiles (1024)
//   [10240, 14336)  : Wo tiles (4096)
// ---------------------------------------------------------------------------
constexpr int PREP_XBLK = 4096;
constexpr int PREP_TOT  = PREP_XBLK + 10240;

__global__ __launch_bounds__(256) void prep_kernel(
    const float* __restrict__ X,
    const float* __restrict__ Wq, const float* __restrict__ Wk,
    const float* __restrict__ Wv, const float* __restrict__ Wo,
    __nv_bfloat16* __restrict__ Ahi, __nv_bfloat16* __restrict__ Alo,
    __nv_bfloat16* __restrict__ WqkvTh, __nv_bfloat16* __restrict__ WqkvTl,
    __nv_bfloat16* __restrict__ WoTh,   __nv_bfloat16* __restrict__ WoTl)
{
    __shared__ float tbuf[32][33];
    const int tx = threadIdx.x & 31;
    const int ty = threadIdx.x >> 5;

    if (blockIdx.x < PREP_XBLK) {
        // input split: grid-strided over n4 = 4M float4
        const int n4 = B_ * S_ * HID_ / 4;
        int i = blockIdx.x * 256 + threadIdx.x;
        int stride = PREP_XBLK * 256;
        for (; i < n4; i += stride) {
            float4 v = ((const float4*)X)[i];
            __nv_bfloat16 h0, h1, h2, h3, l0, l1, l2, l3;
            split2(v.x, h0, l0); split2(v.y, h1, l1);
            split2(v.z, h2, l2); split2(v.w, h3, l3);
            ((__nv_bfloat162*)Ahi)[i * 2]     = __halves2bfloat162(h0, h1);
            ((__nv_bfloat162*)Ahi)[i * 2 + 1] = __halves2bfloat162(h2, h3);
            ((__nv_bfloat162*)Alo)[i * 2]     = __halves2bfloat162(l0, l1);
            ((__nv_bfloat162*)Alo)[i * 2 + 1] = __halves2bfloat162(l2, l3);
        }
        return;
    }

    int tile = blockIdx.x - PREP_XBLK;
    const float* W;
    __nv_bfloat16 *dh, *dl;
    int Nd, ntile_n, dest_row_off;

    if (tile < 4096) {                       // Wq
        W = Wq; dh = WqkvTh; dl = WqkvTl;
        Nd = H_ * D_; ntile_n = Nd / 32; dest_row_off = 0;
    } else if (tile < 5120) {                // Wk
        tile -= 4096;
        W = Wk; dh = WqkvTh; dl = WqkvTl;
        Nd = KV_ * D_; ntile_n = Nd / 32; dest_row_off = KOFF;
    } else if (tile < 6144) {                // Wv
        tile -= 5120;
        W = Wv; dh = WqkvTh; dl = WqkvTl;
        Nd = KV_ * D_; ntile_n = Nd / 32; dest_row_off = VOFF;
    } else {                                 // Wo
        tile -= 6144;
        W = Wo; dh = WoTh; dl = WoTl;
        Nd = HID_; ntile_n = Nd / 32; dest_row_off = 0;
    }
    const int Kd = 2048;
    const int bn = (tile % ntile_n) * 32;
    const int bk = (tile / ntile_n) * 32;

    #pragma unroll
    for (int i = ty; i < 32; i += 8)
        tbuf[i][tx] = W[(size_t)(bk + i) * Nd + bn + tx];
    __syncthreads();
    #pragma unroll
    for (int i = ty; i < 32; i += 8) {
        float v = tbuf[tx][i];
        __nv_bfloat16 h, l;
        split2(v, h, l);
        size_t o = (size_t)(dest_row_off + bn + i) * Kd + bk + tx;
        dh[o] = h;
        dl[o] = l;
    }
}

// ---------------------------------------------------------------------------
// Pipelined mma.sync GEMM: C = A @ B^T, bf16x3 (pass-major stages).
// CTA 128x128, 8 warps, 2-stage cp.async double buffer; ldmatrix fragments.
// 73728 B dyn smem -> 2 CTAs/SM.  (R7 config — proven optimal across probes)
// ---------------------------------------------------------------------------
constexpr int MMP   = 72;
constexpr int MMT   = 128 * MMP;        // 9216 bf16 per tile
constexpr int MMSTG = 2 * MMT;          // A + B tile
constexpr int MM_SMEM = 2 * MMSTG * 2;  // 73728 bytes

__global__ __launch_bounds__(256, 2) void mm_mma_kernel(
    const __nv_bfloat16* __restrict__ Ahi, const __nv_bfloat16* __restrict__ Alo,
    const __nv_bfloat16* __restrict__ Bhi, const __nv_bfloat16* __restrict__ Blo,
    float* __restrict__ C, int M, int N, int K)
{
    extern __shared__ char smc[];
    __nv_bfloat16* bufs = (__nv_bfloat16*)smc;   // 2 stages of MMSTG

    const int tid  = threadIdx.x;
    const int wid  = tid >> 5;
    const int lane = tid & 31;
    const int g    = lane >> 2;
    const int t    = lane & 3;
    const int wr   = wid >> 1;
    const int wc   = wid & 1;
    const int m0 = blockIdx.y * 128;
    const int n0 = blockIdx.x * 128;

    const int lm_r = lane & 15;
    const int lm_c = (lane >> 4) * 8;

    float acc[2][8][4];
    #pragma unroll
    for (int mb = 0; mb < 2; mb++)
        #pragma unroll
        for (int nb = 0; nb < 8; nb++)
            #pragma unroll
            for (int e = 0; e < 4; e++) acc[mb][nb][e] = 0.f;

    const int cpp   = K / 64;
    const int total = 3 * cpp;

    auto issue = [&](int s) {
        const int pass = s / cpp;
        const int kc   = (s - pass * cpp) * 64;
        const __nv_bfloat16* Ap = (pass == 2) ? Alo : Ahi;
        const __nv_bfloat16* Bp = (pass == 1) ? Blo : Bhi;
        __nv_bfloat16* st = bufs + (s & 1) * MMSTG;
        #pragma unroll
        for (int i = 0; i < 4; i++) {
            int idx = tid + i * 256;
            int row = idx >> 3;
            int c   = (idx & 7) * 8;
            cp16(st + row * MMP + c,       &Ap[(size_t)(m0 + row) * K + kc + c]);
            cp16(st + MMT + row * MMP + c, &Bp[(size_t)(n0 + row) * K + kc + c]);
        }
        CP_COMMIT();
    };

    issue(0);

    for (int s = 0; s < total; ++s) {
        if (s + 1 < total) { issue(s + 1); CP_WAIT(1); }
        else               { CP_WAIT(0); }
        __syncthreads();

        const __nv_bfloat16* As = bufs + (s & 1) * MMSTG;
        const __nv_bfloat16* Bs = As + MMT;
        #pragma unroll
        for (int ks = 0; ks < 4; ks++) {
            const int k0 = ks * 16;
            uint32_t a[2][4];
            #pragma unroll
            for (int mb = 0; mb < 2; mb++)
                ldmx4(a[mb], &As[(32 * wr + 16 * mb + lm_r) * MMP + k0 + lm_c]);
            uint32_t bb[4][4];
            #pragma unroll
            for (int p = 0; p < 4; p++)
                ldmx4(bb[p], &Bs[(64 * wc + 16 * p + lm_r) * MMP + k0 + lm_c]);
            #pragma unroll
            for (int p = 0; p < 4; p++) {
                mma_bf16(acc[0][2 * p],     a[0], bb[p][0], bb[p][2]);
                mma_bf16(acc[0][2 * p + 1], a[0], bb[p][1], bb[p][3]);
                mma_bf16(acc[1][2 * p],     a[1], bb[p][0], bb[p][2]);
                mma_bf16(acc[1][2 * p + 1], a[1], bb[p][1], bb[p][3]);
            }
        }
        __syncthreads();
    }

    #pragma unroll
    for (int mb = 0; mb < 2; mb++) {
        int row0 = m0 + 32 * wr + 16 * mb + g;
        #pragma unroll
        for (int nb = 0; nb < 8; nb++) {
            int col = n0 + 64 * wc + 8 * nb + 2 * t;
            *(float2*)&C[(size_t)row0 * N + col] =
                make_float2(acc[mb][nb][0], acc[mb][nb][1]);
            *(float2*)&C[(size_t)(row0 + 8) * N + col] =
                make_float2(acc[mb][nb][2], acc[mb][nb][3]);
        }
    }
}

// ---------------------------------------------------------------------------
// Fused RMSNorm+RoPE (Q and K) + V-transpose split, ONE launch.
// Block ranges (256 threads):
//   [0, NR_QBLK)                      : q rows
//   [NR_QBLK, NR_QBLK+NR_KBLK)        : k rows
//   [NR_QBLK+NR_KBLK, +VT_BLK)        : vt transpose tiles
// ---------------------------------------------------------------------------
constexpr int NR_QBLK = (B_ * S_ * H_) / 8;    // 16384
constexpr int NR_KBLK = (B_ * S_ * KV_) / 8;   // 4096
constexpr int VT_BLK  = (S_ / 32) * (D_ / 32) * (B_ * KV_);  // 4096
constexpr int NRV_TOT = NR_QBLK + NR_KBLK + VT_BLK;          // 24576

__global__ __launch_bounds__(256) void norm_rope_vt_kernel(
    const float* __restrict__ qkv,
    const float* __restrict__ cosb, const float* __restrict__ sinb,
    const float* __restrict__ qw, const float* __restrict__ kw,
    __nv_bfloat16* __restrict__ qhi, __nv_bfloat16* __restrict__ qlo,
    __nv_bfloat16* __restrict__ khi, __nv_bfloat16* __restrict__ klo)
{
    if (blockIdx.x >= NR_QBLK + NR_KBLK) {
        // ---- vt_split part ----
        __shared__ float tb[32][33];
        int v = blockIdx.x - (NR_QBLK + NR_KBLK);
        const int xs = v & 63;          // S_/32 = 64
        const int yd = (v >> 6) & 3;    // D_/32 = 4
        const int z  = v >> 8;          // B_*KV_ = 16
        const int b  = z / KV_;
        const int kv = z % KV_;
        const int s0 = xs * 32;
        const int d0 = yd * 32;
        const int tx = threadIdx.x & 31;
        const int ty = threadIdx.x >> 5;
        #pragma unroll
        for (int i = ty; i < 32; i += 8)
            tb[i][tx] = qkv[((size_t)b * S_ + s0 + i) * NQKV + VOFF + kv * D_ + d0 + tx];
        __syncthreads();
        #pragma unroll
        for (int i = ty; i < 32; i += 8) {
            float val = tb[tx][i];
            __nv_bfloat16 h, l;
            split2(val, h, l);
            size_t o = (((size_t)b * KV_ + kv) * D_ + d0 + i) * S_ + s0 + tx;
            g_vthi[o] = h;
            g_vtlo[o] = l;
        }
        return;
    }

    // ---- norm+rope part ----
    const bool is_q = blockIdx.x < NR_QBLK;
    const int blk   = is_q ? blockIdx.x : blockIdx.x - NR_QBLK;
    const int nheads = is_q ? H_ : KV_;
    const float* x  = is_q ? qkv : qkv + KOFF;
    const float* w  = is_q ? qw : kw;
    __nv_bfloat16* hi = is_q ? qhi : khi;
    __nv_bfloat16* lo = is_q ? qlo : klo;

    const int warp = (blk * 256 + (int)threadIdx.x) >> 5;
    const int lane = threadIdx.x & 31;

    const int bs   = warp / nheads;
    const int head = warp - bs * nheads;
    const int s    = bs % S_;

    const float* row = x + (size_t)bs * NQKV + (size_t)head * D_;
    size_t obase = (size_t)bs * nheads * D_ + (size_t)head * D_;

    float x0 = row[lane];
    float x1 = row[lane + 32];
    float x2 = row[lane + 64];
    float x3 = row[lane + 96];

    float ss = x0 * x0 + x1 * x1 + x2 * x2 + x3 * x3;
    #pragma unroll
    for (int o = 16; o > 0; o >>= 1) ss += __shfl_xor_sync(0xffffffffu, ss, o);
    float inv = rsqrtf(ss * (1.0f / (float)D_) + EPS_);

    float n0 = x0 * inv * w[lane];
    float n1 = x1 * inv * w[lane + 32];
    float n2 = x2 * inv * w[lane + 64];
    float n3 = x3 * inv * w[lane + 96];

    const float* cr = cosb + (size_t)s * D_;
    const float* sr = sinb + (size_t)s * D_;

    float r0 = n0 * cr[lane]      - n2 * sr[lane];
    float r1 = n1 * cr[lane + 32] - n3 * sr[lane + 32];
    float r2 = n2 * cr[lane + 64] + n0 * sr[lane + 64];
    float r3 = n3 * cr[lane + 96] + n1 * sr[lane + 96];

    __nv_bfloat16 h, l;
    split2(r0, h, l); hi[obase + lane]      = h; lo[obase + lane]      = l;
    split2(r1, h, l); hi[obase + lane + 32] = h; lo[obase + lane + 32] = l;
    split2(r2, h, l); hi[obase + lane + 64] = h; lo[obase + lane + 64] = l;
    split2(r3, h, l); hi[obase + lane + 96] = h; lo[obase + lane + 96] = l;
}

// ---------------------------------------------------------------------------
// Flash attention, bf16x3, BM=128, warp-owns-rows layout (R7 — proven optimal).
// ---------------------------------------------------------------------------
constexpr int APIT = 136;
constexpr int TPIT = 72;
constexpr int AQSZ = 128 * APIT;   // Q tile (128 rows)
constexpr int AKSZ = 64 * APIT;    // K tile (64 tokens)
constexpr int AVSZ = 128 * TPIT;   // Vt tile (128 d x 64 tokens)
constexpr int ATT_SMEM = (2 * AQSZ + 2 * AKSZ + 2 * AVSZ) * 2;  // 141312 B

__global__ __launch_bounds__(256) void attn_mma_kernel()
{
    extern __shared__ char smc[];
    __nv_bfloat16* Qh = (__nv_bfloat16*)smc;
    __nv_bfloat16* Ql = Qh + AQSZ;
    __nv_bfloat16* Kh = Ql + AQSZ;
    __nv_bfloat16* Kl = Kh + AKSZ;
    __nv_bfloat16* Vh = Kl + AKSZ;
    __nv_bfloat16* Vl = Vh + AVSZ;

    const int tid  = threadIdx.x;
    const int wid  = tid >> 5;
    const int lane = tid & 31;
    const int g    = lane >> 2;
    const int t    = lane & 3;

    const int m0  = blockIdx.x * 128;
    const int h   = blockIdx.y;
    const int b   = blockIdx.z;
    const int kvh = h / G_;

    const int lm_r = lane & 15;
    const int lm_c = (lane >> 4) * 8;

    // stage Q (128 rows x 128 d, hi+lo)
    {
        const __nv_bfloat16* qh = g_qhi + (((size_t)b * S_ + m0) * H_ + h) * D_;
        const __nv_bfloat16* ql = g_qlo + (((size_t)b * S_ + m0) * H_ + h) * D_;
        #pragma unroll
        for (int i = 0; i < 8; i++) {
            int idx = tid + i * 256;
            int r   = idx >> 4;
            int c   = (idx & 15) * 8;
            *(uint4*)&Qh[r * APIT + c] = *(const uint4*)&qh[(size_t)r * H_ * D_ + c];
            *(uint4*)&Ql[r * APIT + c] = *(const uint4*)&ql[(size_t)r * H_ * D_ + c];
        }
    }

    float o[16][4];
    #pragma unroll
    for (int j = 0; j < 16; j++)
        #pragma unroll
        for (int e = 0; e < 4; e++) o[j][e] = 0.f;
    float rmx0 = -3.0e38f, rmx1 = -3.0e38f;
    float rsm0 = 0.f, rsm1 = 0.f;

    const __nv_bfloat16* khb = g_khi + ((size_t)b * S_ * KV_ + kvh) * D_;
    const __nv_bfloat16* klb = g_klo + ((size_t)b * S_ * KV_ + kvh) * D_;
    const __nv_bfloat16* vhb = g_vthi + ((size_t)b * KV_ + kvh) * D_ * S_;
    const __nv_bfloat16* vlb = g_vtlo + ((size_t)b * KV_ + kvh) * D_ * S_;

    for (int t0 = 0; t0 < S_; t0 += 64) {
        __syncthreads();   // previous tile's V reads done before overwrite
        #pragma unroll
        for (int i = 0; i < 4; i++) {
            int idx = tid + i * 256;
            int r   = idx >> 4;
            int c   = (idx & 15) * 8;
            size_t go = (size_t)(t0 + r) * KV_ * D_ + c;
            *(uint4*)&Kh[r * APIT + c] = *(const uint4*)&khb[go];
            *(uint4*)&Kl[r * APIT + c] = *(const uint4*)&klb[go];
            int d  = idx >> 3;
            int c2 = (idx & 7) * 8;
            size_t gv = (size_t)d * S_ + t0 + c2;
            *(uint4*)&Vh[d * TPIT + c2] = *(const uint4*)&vhb[gv];
            *(uint4*)&Vl[d * TPIT + c2] = *(const uint4*)&vlb[gv];
        }
        __syncthreads();

        // ---- S = Q @ K^T (bf16x3, ldmatrix) ----
        float sacc[8][4];
        #pragma unroll
        for (int j = 0; j < 8; j++)
            #pragma unroll
            for (int e = 0; e < 4; e++) sacc[j][e] = 0.f;

        #pragma unroll
        for (int pass = 0; pass < 3; pass++) {
            const __nv_bfloat16* Aq = (pass == 2) ? Ql : Qh;
            const __nv_bfloat16* Bk = (pass == 1) ? Kl : Kh;
            #pragma unroll
            for (int ks = 0; ks < 8; ks++) {
                const int k0 = ks * 16;
                uint32_t a[4];
                ldmx4(a, &Aq[(16 * wid + lm_r) * APIT + k0 + lm_c]);
                uint32_t bb[4][4];
                #pragma unroll
                for (int p = 0; p < 4; p++)
                    ldmx4(bb[p], &Bk[(16 * p + lm_r) * APIT + k0 + lm_c]);
                #pragma unroll
                for (int p = 0; p < 4; p++) {
                    mma_bf16(sacc[2 * p],     a, bb[p][0], bb[p][2]);
                    mma_bf16(sacc[2 * p + 1], a, bb[p][1], bb[p][3]);
                }
            }
        }

        // ---- in-warp online softmax ----
        float mx0 = -3.0e38f, mx1 = -3.0e38f;
        #pragma unroll
        for (int j = 0; j < 8; j++) {
            #pragma unroll
            for (int e = 0; e < 4; e++) sacc[j][e] *= SCALE_;
            mx0 = fmaxf(mx0, fmaxf(sacc[j][0], sacc[j][1]));
            mx1 = fmaxf(mx1, fmaxf(sacc[j][2], sacc[j][3]));
        }
        mx0 = fmaxf(mx0, __shfl_xor_sync(0xffffffffu, mx0, 1));
        mx0 = fmaxf(mx0, __shfl_xor_sync(0xffffffffu, mx0, 2));
        mx1 = fmaxf(mx1, __shfl_xor_sync(0xffffffffu, mx1, 1));
        mx1 = fmaxf(mx1, __shfl_xor_sync(0xffffffffu, mx1, 2));

        float m0n = fmaxf(rmx0, mx0);
        float m1n = fmaxf(rmx1, mx1);
        float corr0 = __expf(rmx0 - m0n);
        float corr1 = __expf(rmx1 - m1n);

        // exp + register split of P into hi/lo A-fragment halves
        uint32_t ph0[8], ph1[8], pl0[8], pl1[8];
        float sum0 = 0.f, sum1 = 0.f;
        #pragma unroll
        for (int j = 0; j < 8; j++) {
            float p0 = __expf(sacc[j][0] - m0n);
            float p1 = __expf(sacc[j][1] - m0n);
            float p2 = __expf(sacc[j][2] - m1n);
            float p3 = __expf(sacc[j][3] - m1n);
            sum0 += p0 + p1;
            sum1 += p2 + p3;
            __nv_bfloat16 h0, h1, l0, l1;
            split2(p0, h0, l0); split2(p1, h1, l1);
            ph0[j] = packbf(h0, h1); pl0[j] = packbf(l0, l1);
            split2(p2, h0, l0); split2(p3, h1, l1);
            ph1[j] = packbf(h0, h1); pl1[j] = packbf(l0, l1);
        }
        sum0 += __shfl_xor_sync(0xffffffffu, sum0, 1);
        sum0 += __shfl_xor_sync(0xffffffffu, sum0, 2);
        sum1 += __shfl_xor_sync(0xffffffffu, sum1, 1);
        sum1 += __shfl_xor_sync(0xffffffffu, sum1, 2);

        rsm0 = rsm0 * corr0 + sum0;
        rsm1 = rsm1 * corr1 + sum1;
        rmx0 = m0n;
        rmx1 = m1n;

        #pragma unroll
        for (int j = 0; j < 16; j++) {
            o[j][0] *= corr0; o[j][1] *= corr0;
            o[j][2] *= corr1; o[j][3] *= corr1;
        }

        // ---- O += P @ V (bf16x3, P from registers) ----
        #pragma unroll
        for (int pass = 0; pass < 3; pass++) {
            const uint32_t* a0 = (pass == 2) ? pl0 : ph0;
            const uint32_t* a1 = (pass == 2) ? pl1 : ph1;
            const __nv_bfloat16* Vb = (pass == 1) ? Vl : Vh;
            #pragma unroll
            for (int ks = 0; ks < 4; ks++) {
                const int k0 = ks * 16;
                uint32_t a[4];
                a[0] = a0[2 * ks];
                a[1] = a1[2 * ks];
                a[2] = a0[2 * ks + 1];
                a[3] = a1[2 * ks + 1];
                #pragma unroll
                for (int p = 0; p < 8; p++) {
                    uint32_t bb[4];
                    ldmx4(bb, &Vb[(16 * p + lm_r) * TPIT + k0 + lm_c]);
                    mma_bf16(o[2 * p],     a, bb[0], bb[2]);
                    mma_bf16(o[2 * p + 1], a, bb[1], bb[3]);
                }
            }
        }
    }

    // epilogue: write bf16 hi/lo split directly (input to Wo GEMM)
    float inv0 = 1.0f / rsm0;
    float inv1 = 1.0f / rsm1;
    size_t row0 = ((size_t)b * S_ + m0 + 16 * wid + g) * H_ * D_;
    size_t row1 = row0 + (size_t)8 * H_ * D_;
    #pragma unroll
    for (int j = 0; j < 16; j++) {
        int col = h * D_ + 8 * j + 2 * t;
        __nv_bfloat16 h0, h1, l0, l1;
        split2(o[j][0] * inv0, h0, l0);
        split2(o[j][1] * inv0, h1, l1);
        *(__nv_bfloat162*)&g_Ahi[row0 + col] = __halves2bfloat162(h0, h1);
        *(__nv_bfloat162*)&g_Alo[row0 + col] = __halves2bfloat162(l0, l1);
        split2(o[j][2] * inv1, h0, l0);
        split2(o[j][3] * inv1, h1, l1);
        *(__nv_bfloat162*)&g_Ahi[row1 + col] = __halves2bfloat162(h0, h1);
        *(__nv_bfloat162*)&g_Alo[row1 + col] = __halves2bfloat162(l0, l1);
    }
}

// ---------------------------------------------------------------------------
// Launch
// ---------------------------------------------------------------------------
extern "C" void kernel_launch(void* const* d_in, const int* in_sizes, int n_in,
                              void* d_out, int out_size)
{
    const float* x    = (const float*)d_in[0];
    const float* cosb = (const float*)d_in[1];
    const float* sinb = (const float*)d_in[2];
    const float* Wq   = (const float*)d_in[3];
    const float* Wk   = (const float*)d_in[4];
    const float* Wv   = (const float*)d_in[5];
    const float* Wo   = (const float*)d_in[6];
    const float* qw   = (const float*)d_in[7];
    const float* kw   = (const float*)d_in[8];
    float* out = (float*)d_out;

    float* qkv;
    cudaGetSymbolAddress((void**)&qkv, g_qkv);
    __nv_bfloat16 *Ahi, *Alo, *WqkvTh, *WqkvTl, *WoTh, *WoTl;
    __nv_bfloat16 *qhi, *qlo, *khi, *klo;
    cudaGetSymbolAddress((void**)&Ahi,    g_Ahi);
    cudaGetSymbolAddress((void**)&Alo,    g_Alo);
    cudaGetSymbolAddress((void**)&WqkvTh, g_WqkvT_hi);
    cudaGetSymbolAddress((void**)&WqkvTl, g_WqkvT_lo);
    cudaGetSymbolAddress((void**)&WoTh,   g_WoT_hi);
    cudaGetSymbolAddress((void**)&WoTl,   g_WoT_lo);
    cudaGetSymbolAddress((void**)&qhi,    g_qhi);
    cudaGetSymbolAddress((void**)&qlo,    g_qlo);
    cudaGetSymbolAddress((void**)&khi,    g_khi);
    cudaGetSymbolAddress((void**)&klo,    g_klo);

    const int M = B_ * S_;

    cudaFuncSetAttribute(mm_mma_kernel,
                         cudaFuncAttributeMaxDynamicSharedMemorySize, MM_SMEM);
    cudaFuncSetAttribute(attn_mma_kernel,
                         cudaFuncAttributeMaxDynamicSharedMemorySize, ATT_SMEM);

    // Prep: input split + all weight splits (one launch)
    prep_kernel<<<PREP_TOT, 256>>>(x, Wq, Wk, Wv, Wo,
                                   Ahi, Alo, WqkvTh, WqkvTl, WoTh, WoTl);

    // Fused QKV projection (one GEMM, N=3072)
    mm_mma_kernel<<<dim3(NQKV / 128, M / 128), 256, MM_SMEM>>>(
        Ahi, Alo, WqkvTh, WqkvTl, qkv, M, NQKV, HID_);

    // RMSNorm + RoPE (Q,K) + V transpose split (one launch)
    norm_rope_vt_kernel<<<NRV_TOT, 256>>>(
        qkv, cosb, sinb, qw, kw, qhi, qlo, khi, klo);

    // Attention (R7 config; writes bf16 hi/lo split directly into Ahi/Alo)
    attn_mma_kernel<<<dim3(S_ / 128, H_, B_), 256, ATT_SMEM>>>();

    // Output projection
    mm_mma_kernel<<<dim3(HID_ / 128, M / 128), 256, MM_SMEM>>>(
        Ahi, Alo, WoTh, WoTl, out, M, HID_, HID_);
}